// round 3
// baseline (speedup 1.0000x reference)
#include <cuda_runtime.h>
#include <mma.h>
#include <cstdint>
#include <cstddef>

using namespace nvcuda;

// Problem constants
#define B   4
#define S   2048
#define E   2048
#define H   16
#define DH  128
#define BS  (B*S)   // 8192

// Scratch for projected Q/K/V in [b*H+h, S, DH] layout (64 MB each)
__device__ float g_Q[(size_t)B*H*S*DH];
__device__ float g_K[(size_t)B*H*S*DH];
__device__ float g_V[(size_t)B*H*S*DH];

// ---------------------------------------------------------------------------
// cp.async helpers (LDGSTS, 16B)
// ---------------------------------------------------------------------------
__device__ __forceinline__ void cp16(void* smem_dst, const void* gmem_src) {
    unsigned int d = (unsigned int)__cvta_generic_to_shared(smem_dst);
    asm volatile("cp.async.cg.shared.global [%0], [%1], 16;\n" :: "r"(d), "l"(gmem_src));
}
__device__ __forceinline__ void cp_commit() {
    asm volatile("cp.async.commit_group;\n");
}
__device__ __forceinline__ void cp_wait1() {
    asm volatile("cp.async.wait_group 1;\n");
}
__device__ __forceinline__ void cp_wait0() {
    asm volatile("cp.async.wait_group 0;\n");
}

// ---------------------------------------------------------------------------
// Kernel 1: QKV projection GEMM (tf32 WMMA), double-buffered cp.async pipeline
//   Block tile: 128(M) x 256(N = 2 heads x DH) x 16(K), 256 threads, 8 warps
//   arranged 2(m) x 4(n); warp tile 64x64 = 4x4 fragments of m16n16k8.
// ---------------------------------------------------------------------------
#define QBM 128
#define QBN 256
#define QBK 16
#define XS_LD 20     // 128 rows x 20 floats (80B rows, 16B aligned)
#define WS_LD 260    // 16 rows x 260 floats (1040B rows, 16B aligned)
#define XS_STAGE (QBM * XS_LD)              // 2560 floats
#define WS_STAGE (QBK * WS_LD)              // 4160 floats
#define QKV_SMEM_FLOATS (2 * (XS_STAGE + WS_STAGE))
#define QKV_SMEM_BYTES  (QKV_SMEM_FLOATS * 4)   // 53760 B

__global__ __launch_bounds__(256, 1) void qkv_kernel(
    const float* __restrict__ X,
    const float* __restrict__ Wq,
    const float* __restrict__ Wk,
    const float* __restrict__ Wv)
{
    extern __shared__ float sm[];
    float* Xs[2] = { sm,                         sm + XS_STAGE };
    float* Ws[2] = { sm + 2 * XS_STAGE,          sm + 2 * XS_STAGE + WS_STAGE };

    const int hp   = blockIdx.x;   // head pair 0..7
    const int mblk = blockIdx.y;   // 128-row block of X (0..63)
    const int z    = blockIdx.z;   // 0=Q, 1=K, 2=V
    const int h0   = hp * 2;

    const float* Wz  = (z == 0 ? Wq : (z == 1 ? Wk : Wv));
    const float* Wb  = Wz + (size_t)h0 * E * DH;      // head h0 base
    float*       Out = (z == 0 ? g_Q : (z == 1 ? g_K : g_V));

    const int tx     = threadIdx.x;
    const int wid    = tx >> 5;
    const int warp_m = wid >> 2;   // 0..1 : 64 rows
    const int warp_n = wid & 3;    // 0..3 : 64 cols
    const int m0     = mblk * QBM;

    wmma::fragment<wmma::accumulator, 16, 16, 8, float> acc[4][4];
    #pragma unroll
    for (int i = 0; i < 4; i++)
        #pragma unroll
        for (int j = 0; j < 4; j++)
            wmma::fill_fragment(acc[i][j], 0.0f);

    // loader coords
    const int xrow = tx >> 2;          // 0..63 (two rows: +0, +64)
    const int xc4  = (tx & 3) * 4;     // float col 0,4,8,12

    const float* Xg = X + (size_t)m0 * E;

    // issue loads for stage `st` of k-tile `kt`
    auto issue = [&](int kt, int st) {
        const float* Xsrc = Xg + (size_t)kt * QBK;
        #pragma unroll
        for (int i = 0; i < 2; i++) {
            int row = xrow + 64 * i;
            cp16(Xs[st] + row * XS_LD + xc4, Xsrc + (size_t)row * E + xc4);
        }
        #pragma unroll
        for (int p = 0; p < 4; p++) {
            int idx  = tx + 256 * p;
            int erow = idx >> 6;          // 0..15
            int c4   = idx & 63;          // 0..63 -> col = c4*4 in [0,256)
            int head = c4 >> 5;           // 0 or 1
            const float* src = Wb + (size_t)head * E * DH
                             + (size_t)(kt * QBK + erow) * DH + (c4 & 31) * 4;
            cp16(Ws[st] + erow * WS_LD + c4 * 4, src);
        }
        cp_commit();
    };

    const int NK = E / QBK;  // 128
    issue(0, 0);

    for (int kt = 0; kt < NK; kt++) {
        const int st = kt & 1;
        if (kt + 1 < NK) {
            issue(kt + 1, st ^ 1);
            cp_wait1();
        } else {
            cp_wait0();
        }
        __syncthreads();

        const float* Xt = Xs[st];
        const float* Wt = Ws[st];
        #pragma unroll
        for (int kk = 0; kk < 2; kk++) {
            wmma::fragment<wmma::matrix_a, 16, 16, 8, wmma::precision::tf32, wmma::row_major> af[4];
            wmma::fragment<wmma::matrix_b, 16, 16, 8, wmma::precision::tf32, wmma::row_major> bf[4];
            #pragma unroll
            for (int mi = 0; mi < 4; mi++) {
                wmma::load_matrix_sync(af[mi], Xt + (warp_m * 64 + mi * 16) * XS_LD + kk * 8, XS_LD);
                #pragma unroll
                for (int e = 0; e < af[mi].num_elements; e++)
                    af[mi].x[e] = wmma::__float_to_tf32(af[mi].x[e]);
            }
            #pragma unroll
            for (int ni = 0; ni < 4; ni++) {
                wmma::load_matrix_sync(bf[ni], Wt + (kk * 8) * WS_LD + warp_n * 64 + ni * 16, WS_LD);
                #pragma unroll
                for (int e = 0; e < bf[ni].num_elements; e++)
                    bf[ni].x[e] = wmma::__float_to_tf32(bf[ni].x[e]);
            }
            #pragma unroll
            for (int mi = 0; mi < 4; mi++)
                #pragma unroll
                for (int ni = 0; ni < 4; ni++)
                    wmma::mma_sync(acc[mi][ni], af[mi], bf[ni], acc[mi][ni]);
        }
        __syncthreads();
    }

    // epilogue: Out[(bb*H + h0 + head), s, d]; 128-row tile never crosses b
    const int bb = m0 / S;
    const int s0 = m0 % S;
    #pragma unroll
    for (int ni = 0; ni < 4; ni++) {
        const int ncol = warp_n * 64 + ni * 16;   // 0..255, 16-aligned
        const int head = ncol >> 7;
        const int d    = ncol & 127;
        float* Obase = Out + ((size_t)(bb * H + h0 + head) * S + s0) * DH + d;
        #pragma unroll
        for (int mi = 0; mi < 4; mi++) {
            float* p = Obase + (size_t)(warp_m * 64 + mi * 16) * DH;
            wmma::store_matrix_sync(p, acc[mi][ni], DH, wmma::mem_row_major);
        }
    }
}

// ---------------------------------------------------------------------------
// Kernel 2: causal flash attention, fp32 SIMT with vectorized smem reads
//   grid (S/64, B*H), 256 threads. Thread (r = t/4, c = t%4) owns output row
//   q0+r, CONTIGUOUS cols d in [32c, 32c+32). All smem reads are LDS.128
//   broadcasts (4 distinct 16B addresses per warp) -> FFMA-pipe bound.
// ---------------------------------------------------------------------------
__global__ __launch_bounds__(256, 1) void attn_kernel(float* __restrict__ out)
{
    extern __shared__ float sm[];
    float* Ks = sm;              // 64 x 128
    float* Vs = sm + 64 * 128;   // 64 x 128

    const int qb = blockIdx.x;
    const int bh = blockIdx.y;
    const int b  = bh >> 4;      // H = 16
    const int h  = bh & 15;
    const int q0 = qb * 64;
    const int t  = threadIdx.x;
    const int r  = t >> 2;       // 0..63
    const int c  = t & 3;        // 0..3
    const int d0 = c * 32;

    // Q row slice into registers (contiguous d = d0..d0+31)
    const float4* Qg = (const float4*)(g_Q + ((size_t)bh * S + q0 + r) * DH + d0);
    float4 q[8];
    #pragma unroll
    for (int i = 0; i < 8; i++) q[i] = Qg[i];

    float4 acc[8];
    #pragma unroll
    for (int i = 0; i < 8; i++) acc[i] = make_float4(0.f, 0.f, 0.f, 0.f);
    float mrow = -3.0e38f, lrow = 0.0f;

    const float scale = 0.08838834764831845f;  // 1/sqrt(128)

    for (int kb = 0; kb <= qb; kb++) {
        const int k0 = kb * 64;
        const float4* Kg = (const float4*)(g_K + ((size_t)bh * S + k0) * DH);
        const float4* Vg = (const float4*)(g_V + ((size_t)bh * S + k0) * DH);

        __syncthreads();   // previous tile fully consumed
        #pragma unroll
        for (int i = 0; i < 8; i++) {
            ((float4*)Ks)[t + 256 * i] = Kg[t + 256 * i];
            ((float4*)Vs)[t + 256 * i] = Vg[t + 256 * i];
        }
        __syncthreads();

        // scores: s[j] = (Q[r] . K[j]) * scale (4-lane split over d, bfly reduce)
        float s[64];
        #pragma unroll 4
        for (int j = 0; j < 64; j++) {
            const float4* kr = (const float4*)(Ks + j * 128 + d0);
            float p0 = 0.f, p1 = 0.f, p2 = 0.f, p3 = 0.f;
            #pragma unroll
            for (int i = 0; i < 8; i++) {
                float4 kv = kr[i];
                p0 += q[i].x * kv.x;
                p1 += q[i].y * kv.y;
                p2 += q[i].z * kv.z;
                p3 += q[i].w * kv.w;
            }
            float pv = (p0 + p1) + (p2 + p3);
            pv += __shfl_xor_sync(0xffffffffu, pv, 1);
            pv += __shfl_xor_sync(0xffffffffu, pv, 2);
            s[j] = pv * scale;
        }

        if (kb == qb) {  // diagonal tile: causal mask (k0 == q0)
            #pragma unroll
            for (int j = 0; j < 64; j++)
                if (j > r) s[j] = -3.0e38f;
        }

        // online softmax
        float mnew = mrow;
        #pragma unroll
        for (int j = 0; j < 64; j++) mnew = fmaxf(mnew, s[j]);
        const float corr = __expf(mrow - mnew);
        lrow *= corr;
        #pragma unroll
        for (int i = 0; i < 8; i++) {
            acc[i].x *= corr; acc[i].y *= corr; acc[i].z *= corr; acc[i].w *= corr;
        }
        mrow = mnew;

        #pragma unroll 4
        for (int j = 0; j < 64; j++) {
            const float p = __expf(s[j] - mnew);
            lrow += p;
            const float4* vr = (const float4*)(Vs + j * 128 + d0);
            #pragma unroll
            for (int i = 0; i < 8; i++) {
                float4 vv = vr[i];
                acc[i].x += p * vv.x;
                acc[i].y += p * vv.y;
                acc[i].z += p * vv.z;
                acc[i].w += p * vv.w;
            }
        }
    }

    // epilogue: normalize, round(x, 4) like the reference, write [B,S,H*DH]
    const float inv = 1.0f / lrow;
    float4* Og = (float4*)(out + (size_t)(b * S + q0 + r) * (H * DH) + h * DH + d0);
    #pragma unroll
    for (int i = 0; i < 8; i++) {
        float4 v = acc[i];
        v.x = rintf(v.x * inv * 1.0e4f) * 1.0e-4f;
        v.y = rintf(v.y * inv * 1.0e4f) * 1.0e-4f;
        v.z = rintf(v.z * inv * 1.0e4f) * 1.0e-4f;
        v.w = rintf(v.w * inv * 1.0e4f) * 1.0e-4f;
        Og[i] = v;
    }
}

// ---------------------------------------------------------------------------
extern "C" void kernel_launch(void* const* d_in, const int* in_sizes, int n_in,
                              void* d_out, int out_size)
{
    const float* X  = (const float*)d_in[0];
    const float* Wq = (const float*)d_in[1];
    const float* Wk = (const float*)d_in[2];
    const float* Wv = (const float*)d_in[3];
    float* out = (float*)d_out;

    cudaFuncSetAttribute(qkv_kernel, cudaFuncAttributeMaxDynamicSharedMemorySize, QKV_SMEM_BYTES);
    cudaFuncSetAttribute(attn_kernel, cudaFuncAttributeMaxDynamicSharedMemorySize, 65536);

    dim3 g1(H / 2, BS / QBM, 3);
    qkv_kernel<<<g1, 256, QKV_SMEM_BYTES>>>(X, Wq, Wk, Wv);

    dim3 g2(S / 64, B * H);
    attn_kernel<<<g2, 256, 65536>>>(out);
}

// round 4
// speedup vs baseline: 5.4273x; 5.4273x over previous
#include <cuda_runtime.h>
#include <mma.h>
#include <cstdint>
#include <cstddef>

using namespace nvcuda;

// Problem constants
#define B   4
#define S   2048
#define E   2048
#define H   16
#define DH  128
#define BS  (B*S)   // 8192

// Scratch for projected Q/K/V in [b*H+h, S, DH] layout (64 MB each)
__device__ float g_Q[(size_t)B*H*S*DH];
__device__ float g_K[(size_t)B*H*S*DH];
__device__ float g_V[(size_t)B*H*S*DH];

// ---------------------------------------------------------------------------
// cp.async helpers (LDGSTS, 16B)
// ---------------------------------------------------------------------------
__device__ __forceinline__ void cp16(void* smem_dst, const void* gmem_src) {
    unsigned int d = (unsigned int)__cvta_generic_to_shared(smem_dst);
    asm volatile("cp.async.cg.shared.global [%0], [%1], 16;\n" :: "r"(d), "l"(gmem_src));
}
__device__ __forceinline__ void cp_commit() {
    asm volatile("cp.async.commit_group;\n");
}
__device__ __forceinline__ void cp_wait1() {
    asm volatile("cp.async.wait_group 1;\n");
}
__device__ __forceinline__ void cp_wait0() {
    asm volatile("cp.async.wait_group 0;\n");
}

// tf32 conversion + raw m16n8k8 tf32 MMA (documented fragment layout)
__device__ __forceinline__ unsigned f2tf(float f) {
    unsigned u; asm("cvt.rna.tf32.f32 %0, %1;" : "=r"(u) : "f"(f)); return u;
}
__device__ __forceinline__ void mma_tf32(float c[4], const unsigned a[4], const unsigned b[2]) {
    asm volatile("mma.sync.aligned.m16n8k8.row.col.f32.tf32.tf32.f32 "
        "{%0,%1,%2,%3}, {%4,%5,%6,%7}, {%8,%9}, {%0,%1,%2,%3};"
        : "+f"(c[0]), "+f"(c[1]), "+f"(c[2]), "+f"(c[3])
        : "r"(a[0]), "r"(a[1]), "r"(a[2]), "r"(a[3]), "r"(b[0]), "r"(b[1]));
}

// ---------------------------------------------------------------------------
// Kernel 1: QKV projection GEMM (tf32 WMMA), double-buffered cp.async pipeline
//   Block tile: 128(M) x 256(N = 2 heads x DH) x 16(K), 256 threads, 8 warps
//   arranged 2(m) x 4(n); warp tile 64x64 = 4x4 fragments of m16n16k8.
// ---------------------------------------------------------------------------
#define QBM 128
#define QBN 256
#define QBK 16
#define XS_LD 20
#define WS_LD 260
#define XS_STAGE (QBM * XS_LD)
#define WS_STAGE (QBK * WS_LD)
#define QKV_SMEM_FLOATS (2 * (XS_STAGE + WS_STAGE))
#define QKV_SMEM_BYTES  (QKV_SMEM_FLOATS * 4)

__global__ __launch_bounds__(256, 1) void qkv_kernel(
    const float* __restrict__ X,
    const float* __restrict__ Wq,
    const float* __restrict__ Wk,
    const float* __restrict__ Wv)
{
    extern __shared__ float sm[];
    float* Xs[2] = { sm,                sm + XS_STAGE };
    float* Ws[2] = { sm + 2 * XS_STAGE, sm + 2 * XS_STAGE + WS_STAGE };

    const int hp   = blockIdx.x;
    const int mblk = blockIdx.y;
    const int z    = blockIdx.z;
    const int h0   = hp * 2;

    const float* Wz  = (z == 0 ? Wq : (z == 1 ? Wk : Wv));
    const float* Wb  = Wz + (size_t)h0 * E * DH;
    float*       Out = (z == 0 ? g_Q : (z == 1 ? g_K : g_V));

    const int tx     = threadIdx.x;
    const int wid    = tx >> 5;
    const int warp_m = wid >> 2;
    const int warp_n = wid & 3;
    const int m0     = mblk * QBM;

    wmma::fragment<wmma::accumulator, 16, 16, 8, float> acc[4][4];
    #pragma unroll
    for (int i = 0; i < 4; i++)
        #pragma unroll
        for (int j = 0; j < 4; j++)
            wmma::fill_fragment(acc[i][j], 0.0f);

    const int xrow = tx >> 2;
    const int xc4  = (tx & 3) * 4;

    const float* Xg = X + (size_t)m0 * E;

    auto issue = [&](int kt, int st) {
        const float* Xsrc = Xg + (size_t)kt * QBK;
        #pragma unroll
        for (int i = 0; i < 2; i++) {
            int row = xrow + 64 * i;
            cp16(Xs[st] + row * XS_LD + xc4, Xsrc + (size_t)row * E + xc4);
        }
        #pragma unroll
        for (int p = 0; p < 4; p++) {
            int idx  = tx + 256 * p;
            int erow = idx >> 6;
            int c4   = idx & 63;
            int head = c4 >> 5;
            const float* src = Wb + (size_t)head * E * DH
                             + (size_t)(kt * QBK + erow) * DH + (c4 & 31) * 4;
            cp16(Ws[st] + erow * WS_LD + c4 * 4, src);
        }
        cp_commit();
    };

    const int NK = E / QBK;
    issue(0, 0);

    for (int kt = 0; kt < NK; kt++) {
        const int st = kt & 1;
        if (kt + 1 < NK) {
            issue(kt + 1, st ^ 1);
            cp_wait1();
        } else {
            cp_wait0();
        }
        __syncthreads();

        const float* Xt = Xs[st];
        const float* Wt = Ws[st];
        #pragma unroll
        for (int kk = 0; kk < 2; kk++) {
            wmma::fragment<wmma::matrix_a, 16, 16, 8, wmma::precision::tf32, wmma::row_major> af[4];
            wmma::fragment<wmma::matrix_b, 16, 16, 8, wmma::precision::tf32, wmma::row_major> bf[4];
            #pragma unroll
            for (int mi = 0; mi < 4; mi++) {
                wmma::load_matrix_sync(af[mi], Xt + (warp_m * 64 + mi * 16) * XS_LD + kk * 8, XS_LD);
                #pragma unroll
                for (int e = 0; e < af[mi].num_elements; e++)
                    af[mi].x[e] = wmma::__float_to_tf32(af[mi].x[e]);
            }
            #pragma unroll
            for (int ni = 0; ni < 4; ni++) {
                wmma::load_matrix_sync(bf[ni], Wt + (kk * 8) * WS_LD + warp_n * 64 + ni * 16, WS_LD);
                #pragma unroll
                for (int e = 0; e < bf[ni].num_elements; e++)
                    bf[ni].x[e] = wmma::__float_to_tf32(bf[ni].x[e]);
            }
            #pragma unroll
            for (int mi = 0; mi < 4; mi++)
                #pragma unroll
                for (int ni = 0; ni < 4; ni++)
                    wmma::mma_sync(acc[mi][ni], af[mi], bf[ni], acc[mi][ni]);
        }
        __syncthreads();
    }

    const int bb = m0 / S;
    const int s0 = m0 % S;
    #pragma unroll
    for (int ni = 0; ni < 4; ni++) {
        const int ncol = warp_n * 64 + ni * 16;
        const int head = ncol >> 7;
        const int d    = ncol & 127;
        float* Obase = Out + ((size_t)(bb * H + h0 + head) * S + s0) * DH + d;
        #pragma unroll
        for (int mi = 0; mi < 4; mi++) {
            float* p = Obase + (size_t)(warp_m * 64 + mi * 16) * DH;
            wmma::store_matrix_sync(p, acc[mi][ni], DH, wmma::mem_row_major);
        }
    }
}

// ---------------------------------------------------------------------------
// Kernel 2: causal flash attention on tensor cores (mma.m16n8k8 tf32)
//   CTA = 64 q-rows of one (b,h). 8 warps = 4(m) x 2(n).
//   O accumulators live in registers across KV tiles (known c-reg row map
//   allows exact per-row rescale). K/V double-buffered via cp.async.
//   Lead dims: Q/K/Ss = 132 / 68 (row stride == 16B mod 128B -> conflict-free
//   a/b fragment loads), V = 136 (== 32B mod 128B -> conflict-free PV b loads).
// ---------------------------------------------------------------------------
#define KLD 132
#define VLD 136
#define SLD 68
#define ATTN_SMEM_FLOATS (64*KLD + 2*64*KLD + 2*64*VLD + 64*SLD + 64 + 64 + 128 + 128)
#define ATTN_SMEM_BYTES  (ATTN_SMEM_FLOATS * 4)   // 189,952 B

__global__ __launch_bounds__(256, 1) void attn_kernel(float* __restrict__ out)
{
    extern __shared__ float sm[];
    float* Qs   = sm;                       // 64*132
    float* Ks   = Qs + 64*KLD;              // 2 x 64*132
    float* Vs   = Ks + 2*64*KLD;            // 2 x 64*136
    float* Ss   = Vs + 2*64*VLD;            // 64*68 (tf32 bits of P)
    float* m_s  = Ss + 64*SLD;              // 64
    float* l_s  = m_s + 64;                 // 64
    float* wmax = l_s + 64;                 // 2*64
    float* wsum = wmax + 128;               // 2*64
    unsigned* Su = reinterpret_cast<unsigned*>(Ss);

    const int qb = blockIdx.x;
    const int bh = blockIdx.y;
    const int b  = bh >> 4;
    const int h  = bh & 15;
    const int q0 = qb * 64;
    const int tid  = threadIdx.x;
    const int lane = tid & 31;
    const int wid  = tid >> 5;
    const int warp_m = wid >> 1;    // 0..3 : 16 rows
    const int warp_n = wid & 1;     // 0..1 : 64 out-cols / 32 score-cols
    const int g  = lane >> 2;       // 0..7
    const int t4 = lane & 3;        // 0..3
    const int m0 = warp_m * 16;
    const int rlo = m0 + g;
    const int rhi = m0 + g + 8;

    if (tid < 64) { m_s[tid] = -3.0e38f; l_s[tid] = 0.0f; }

    // initial loads: Q + K0 + V0 in one cp.async group
    {
        const float* Qg = g_Q + ((size_t)bh * S + q0) * DH;
        const float* Kg = g_K + ((size_t)bh * S) * DH;
        const float* Vg = g_V + ((size_t)bh * S) * DH;
        const int row = tid >> 2, c0 = tid & 3;
        #pragma unroll
        for (int i = 0; i < 8; i++) {
            const int col = (c0 + 4 * i) * 4;
            cp16(Qs + row * KLD + col, Qg + row * DH + col);
            cp16(Ks + row * KLD + col, Kg + row * DH + col);
            cp16(Vs + row * VLD + col, Vg + row * DH + col);
        }
        cp_commit();
    }

    float oacc[8][4];
    #pragma unroll
    for (int i = 0; i < 8; i++)
        #pragma unroll
        for (int j = 0; j < 4; j++) oacc[i][j] = 0.0f;

    const float scale = 0.08838834764831845f;  // 1/sqrt(128)

    for (int kb = 0; kb <= qb; kb++) {
        __syncthreads();   // previous tile fully consumed (safe to overwrite other buffer)
        if (kb < qb) {
            const int st = (kb + 1) & 1;
            const float* Kg = g_K + ((size_t)bh * S + (size_t)(kb + 1) * 64) * DH;
            const float* Vg = g_V + ((size_t)bh * S + (size_t)(kb + 1) * 64) * DH;
            float* Kd = Ks + st * (64 * KLD);
            float* Vd = Vs + st * (64 * VLD);
            const int row = tid >> 2, c0 = tid & 3;
            #pragma unroll
            for (int i = 0; i < 8; i++) {
                const int col = (c0 + 4 * i) * 4;
                cp16(Kd + row * KLD + col, Kg + row * DH + col);
                cp16(Vd + row * VLD + col, Vg + row * DH + col);
            }
            cp_commit();
            cp_wait1();
        } else {
            cp_wait0();
        }
        __syncthreads();

        const float* Kb_ = Ks + (kb & 1) * (64 * KLD);
        const float* Vb_ = Vs + (kb & 1) * (64 * VLD);

        // ---- scores: C[64x64] = Q · K^T ----
        float c[4][4];
        #pragma unroll
        for (int nf = 0; nf < 4; nf++)
            #pragma unroll
            for (int e = 0; e < 4; e++) c[nf][e] = 0.0f;

        #pragma unroll
        for (int ks = 0; ks < 16; ks++) {
            const float* qp = Qs + rlo * KLD + ks * 8 + t4;
            unsigned a[4];
            a[0] = f2tf(qp[0]);
            a[2] = f2tf(qp[4]);
            a[1] = f2tf(qp[8 * KLD]);
            a[3] = f2tf(qp[8 * KLD + 4]);
            #pragma unroll
            for (int nf = 0; nf < 4; nf++) {
                const float* kp = Kb_ + (warp_n * 32 + nf * 8 + g) * KLD + ks * 8 + t4;
                unsigned bb[2] = { f2tf(kp[0]), f2tf(kp[4]) };
                mma_tf32(c[nf], a, bb);
            }
        }

        // scale + causal mask + per-warp row max
        float mx0 = -3.0e38f, mx1 = -3.0e38f;
        #pragma unroll
        for (int nf = 0; nf < 4; nf++) {
            const int col = warp_n * 32 + nf * 8 + 2 * t4;
            #pragma unroll
            for (int e = 0; e < 4; e++) c[nf][e] *= scale;
            if (kb == qb) {
                if (col     > rlo) c[nf][0] = -3.0e38f;
                if (col + 1 > rlo) c[nf][1] = -3.0e38f;
                if (col     > rhi) c[nf][2] = -3.0e38f;
                if (col + 1 > rhi) c[nf][3] = -3.0e38f;
            }
            mx0 = fmaxf(mx0, fmaxf(c[nf][0], c[nf][1]));
            mx1 = fmaxf(mx1, fmaxf(c[nf][2], c[nf][3]));
        }
        mx0 = fmaxf(mx0, __shfl_xor_sync(0xffffffffu, mx0, 1));
        mx0 = fmaxf(mx0, __shfl_xor_sync(0xffffffffu, mx0, 2));
        mx1 = fmaxf(mx1, __shfl_xor_sync(0xffffffffu, mx1, 1));
        mx1 = fmaxf(mx1, __shfl_xor_sync(0xffffffffu, mx1, 2));
        if (t4 == 0) {
            wmax[warp_n * 64 + rlo] = mx0;
            wmax[warp_n * 64 + rhi] = mx1;
        }
        __syncthreads();

        // ---- online softmax ----
        const float mo0 = m_s[rlo], mo1 = m_s[rhi];
        const float mn0 = fmaxf(mo0, fmaxf(wmax[rlo], wmax[64 + rlo]));
        const float mn1 = fmaxf(mo1, fmaxf(wmax[rhi], wmax[64 + rhi]));
        const float cr0 = __expf(mo0 - mn0);
        const float cr1 = __expf(mo1 - mn1);
        float sum0 = 0.0f, sum1 = 0.0f;
        #pragma unroll
        for (int nf = 0; nf < 4; nf++) {
            const int col = warp_n * 32 + nf * 8 + 2 * t4;
            const float p0 = __expf(c[nf][0] - mn0);
            const float p1 = __expf(c[nf][1] - mn0);
            const float p2 = __expf(c[nf][2] - mn1);
            const float p3 = __expf(c[nf][3] - mn1);
            sum0 += p0 + p1;
            sum1 += p2 + p3;
            uint2 lo = make_uint2(f2tf(p0), f2tf(p1));
            uint2 hi = make_uint2(f2tf(p2), f2tf(p3));
            *reinterpret_cast<uint2*>(Su + rlo * SLD + col) = lo;
            *reinterpret_cast<uint2*>(Su + rhi * SLD + col) = hi;
        }
        sum0 += __shfl_xor_sync(0xffffffffu, sum0, 1);
        sum0 += __shfl_xor_sync(0xffffffffu, sum0, 2);
        sum1 += __shfl_xor_sync(0xffffffffu, sum1, 1);
        sum1 += __shfl_xor_sync(0xffffffffu, sum1, 2);
        if (t4 == 0) {
            wsum[warp_n * 64 + rlo] = sum0;
            wsum[warp_n * 64 + rhi] = sum1;
        }
        // rescale O accumulators (rows rlo via c0/c1, rhi via c2/c3)
        #pragma unroll
        for (int nf = 0; nf < 8; nf++) {
            oacc[nf][0] *= cr0; oacc[nf][1] *= cr0;
            oacc[nf][2] *= cr1; oacc[nf][3] *= cr1;
        }
        __syncthreads();

        // ---- PV: O += P · V ----
        #pragma unroll
        for (int ks = 0; ks < 8; ks++) {
            const unsigned* sp = Su + rlo * SLD + ks * 8 + t4;
            unsigned a[4];
            a[0] = sp[0];
            a[2] = sp[4];
            a[1] = sp[8 * SLD];
            a[3] = sp[8 * SLD + 4];
            const float* vp0 = Vb_ + (ks * 8 + t4) * VLD + warp_n * 64 + g;
            const float* vp1 = vp0 + 4 * VLD;
            #pragma unroll
            for (int nf = 0; nf < 8; nf++) {
                unsigned bb[2] = { f2tf(vp0[nf * 8]), f2tf(vp1[nf * 8]) };
                mma_tf32(oacc[nf], a, bb);
            }
        }

        // stats update (single writer per row; separated from readers by syncs)
        if (warp_n == 0 && t4 == 0) {
            m_s[rlo] = mn0;
            l_s[rlo] = l_s[rlo] * cr0 + wsum[rlo] + wsum[64 + rlo];
            m_s[rhi] = mn1;
            l_s[rhi] = l_s[rhi] * cr1 + wsum[rhi] + wsum[64 + rhi];
        }
    }

    __syncthreads();
    const float li0 = 1.0f / l_s[rlo];
    const float li1 = 1.0f / l_s[rhi];
    float* og0 = out + ((size_t)(b * S + q0 + rlo)) * (H * DH) + h * DH + warp_n * 64;
    float* og1 = out + ((size_t)(b * S + q0 + rhi)) * (H * DH) + h * DH + warp_n * 64;
    #pragma unroll
    for (int nf = 0; nf < 8; nf++) {
        const int col = nf * 8 + 2 * t4;
        float2 v0, v1;
        v0.x = rintf(oacc[nf][0] * li0 * 1.0e4f) * 1.0e-4f;
        v0.y = rintf(oacc[nf][1] * li0 * 1.0e4f) * 1.0e-4f;
        v1.x = rintf(oacc[nf][2] * li1 * 1.0e4f) * 1.0e-4f;
        v1.y = rintf(oacc[nf][3] * li1 * 1.0e4f) * 1.0e-4f;
        *reinterpret_cast<float2*>(og0 + col) = v0;
        *reinterpret_cast<float2*>(og1 + col) = v1;
    }
}

// ---------------------------------------------------------------------------
extern "C" void kernel_launch(void* const* d_in, const int* in_sizes, int n_in,
                              void* d_out, int out_size)
{
    const float* X  = (const float*)d_in[0];
    const float* Wq = (const float*)d_in[1];
    const float* Wk = (const float*)d_in[2];
    const float* Wv = (const float*)d_in[3];
    float* out = (float*)d_out;

    cudaFuncSetAttribute(qkv_kernel, cudaFuncAttributeMaxDynamicSharedMemorySize, QKV_SMEM_BYTES);
    cudaFuncSetAttribute(attn_kernel, cudaFuncAttributeMaxDynamicSharedMemorySize, ATTN_SMEM_BYTES);

    dim3 g1(H / 2, BS / QBM, 3);
    qkv_kernel<<<g1, 256, QKV_SMEM_BYTES>>>(X, Wq, Wk, Wv);

    dim3 g2(S / 64, B * H);
    attn_kernel<<<g2, 256, ATTN_SMEM_BYTES>>>(out);
}

// round 5
// speedup vs baseline: 8.8313x; 1.6272x over previous
#include <cuda_runtime.h>
#include <cstdint>
#include <cstddef>

// Problem constants
#define B   4
#define S   2048
#define E   2048
#define H   16
#define DH  128
#define BS  (B*S)   // 8192

// Scratch: projected Q/K/V (tf32 bit patterns) in [b*H+h, S, DH]
__device__ float g_Q[(size_t)B*H*S*DH];
__device__ float g_K[(size_t)B*H*S*DH];
__device__ float g_V[(size_t)B*H*S*DH];
// tf32-converted inputs
__device__ float g_Xc [(size_t)BS*E];
__device__ float g_Wcq[(size_t)H*E*DH];
__device__ float g_Wck[(size_t)H*E*DH];
__device__ float g_Wcv[(size_t)H*E*DH];

// ---------------------------------------------------------------------------
// helpers
// ---------------------------------------------------------------------------
__device__ __forceinline__ void cp16(void* smem_dst, const void* gmem_src) {
    unsigned int d = (unsigned int)__cvta_generic_to_shared(smem_dst);
    asm volatile("cp.async.cg.shared.global [%0], [%1], 16;\n" :: "r"(d), "l"(gmem_src));
}
__device__ __forceinline__ void cp_commit() { asm volatile("cp.async.commit_group;\n"); }
__device__ __forceinline__ void cp_wait1()  { asm volatile("cp.async.wait_group 1;\n"); }
__device__ __forceinline__ void cp_wait0()  { asm volatile("cp.async.wait_group 0;\n"); }

__device__ __forceinline__ unsigned f2tf(float f) {
    unsigned u; asm("cvt.rna.tf32.f32 %0, %1;" : "=r"(u) : "f"(f)); return u;
}
__device__ __forceinline__ void mma_tf32(float c[4], const unsigned a[4], const unsigned b[2]) {
    asm volatile("mma.sync.aligned.m16n8k8.row.col.f32.tf32.tf32.f32 "
        "{%0,%1,%2,%3}, {%4,%5,%6,%7}, {%8,%9}, {%0,%1,%2,%3};"
        : "+f"(c[0]), "+f"(c[1]), "+f"(c[2]), "+f"(c[3])
        : "r"(a[0]), "r"(a[1]), "r"(a[2]), "r"(a[3]), "r"(b[0]), "r"(b[1]));
}

// ---------------------------------------------------------------------------
// Kernel 0: elementwise tf32 pre-conversion (bit patterns stored as float)
// ---------------------------------------------------------------------------
__global__ void tf32_conv(const float* __restrict__ src, float* __restrict__ dst, int n4)
{
    const float4* s = (const float4*)src;
    float4*       d = (float4*)dst;
    for (int i = blockIdx.x * blockDim.x + threadIdx.x; i < n4; i += gridDim.x * blockDim.x) {
        float4 v = s[i];
        v.x = __uint_as_float(f2tf(v.x));
        v.y = __uint_as_float(f2tf(v.y));
        v.z = __uint_as_float(f2tf(v.z));
        v.w = __uint_as_float(f2tf(v.w));
        d[i] = v;
    }
}

// ---------------------------------------------------------------------------
// Kernel 1: QKV projection GEMM on raw m16n8k8 tf32 (inputs pre-converted,
//   NO cvt in inner loop). Block tile 128(M) x 128(N=1 head) x 32(K),
//   256 threads, 8 warps = 4(m) x 2(n), warp tile 32x64. Double-buffered
//   cp.async. 2 CTAs/SM. Output stored already tf32-rounded for attn.
//   Smem lead dims XLD=36, WLD=132 (== 16B mod 128B -> conflict-free).
// ---------------------------------------------------------------------------
#define QM 128
#define QN 128
#define QKC 32
#define XLD 36
#define WLD 132
#define XST (QM*XLD)    // 4608 floats
#define WST (QKC*WLD)   // 4224 floats
#define QKV_SMEM_BYTES ((2*(XST+WST))*4)   // 70,656 B

__global__ __launch_bounds__(256, 2) void qkv_kernel()
{
    extern __shared__ float sm[];
    float* Xs[2] = { sm,           sm + XST };
    float* Ws[2] = { sm + 2*XST,   sm + 2*XST + WST };

    const int h    = blockIdx.x;
    const int mblk = blockIdx.y;
    const int z    = blockIdx.z;

    const float* Wb = (z == 0 ? g_Wcq : (z == 1 ? g_Wck : g_Wcv)) + (size_t)h * E * DH;
    float*      Out = (z == 0 ? g_Q   : (z == 1 ? g_K   : g_V));

    const int tx   = threadIdx.x;
    const int lane = tx & 31;
    const int wid  = tx >> 5;
    const int warp_m = wid >> 1;   // 0..3 : 32 rows
    const int warp_n = wid & 1;    // 0..1 : 64 cols
    const int g  = lane >> 2;
    const int t4 = lane & 3;
    const int m0 = mblk * QM;

    float c[2][8][4];
    #pragma unroll
    for (int mi = 0; mi < 2; mi++)
        #pragma unroll
        for (int ni = 0; ni < 8; ni++)
            #pragma unroll
            for (int e = 0; e < 4; e++) c[mi][ni][e] = 0.0f;

    const float* Xg = g_Xc + (size_t)m0 * E;

    auto issue = [&](int kt, int st) {
        #pragma unroll
        for (int i = 0; i < 4; i++) {
            int idx  = tx + 256 * i;          // 0..1023
            int row  = idx >> 3;              // 0..127
            int col4 = (idx & 7) * 4;         // 0..28
            cp16(Xs[st] + row * XLD + col4, Xg + (size_t)row * E + kt * QKC + col4);
        }
        #pragma unroll
        for (int i = 0; i < 4; i++) {
            int idx = tx + 256 * i;           // 0..1023
            int kr  = idx >> 5;               // 0..31
            int c4  = (idx & 31) * 4;         // 0..124
            cp16(Ws[st] + kr * WLD + c4, Wb + (size_t)(kt * QKC + kr) * DH + c4);
        }
        cp_commit();
    };

    const int NK = E / QKC;   // 64
    issue(0, 0);

    for (int kt = 0; kt < NK; kt++) {
        const int st = kt & 1;
        if (kt + 1 < NK) { issue(kt + 1, st ^ 1); cp_wait1(); }
        else             { cp_wait0(); }
        __syncthreads();

        const float* Xt = Xs[st];
        const float* Wt = Ws[st];
        #pragma unroll
        for (int ks = 0; ks < 4; ks++) {
            unsigned a[2][4];
            #pragma unroll
            for (int mi = 0; mi < 2; mi++) {
                const float* ap = Xt + (warp_m * 32 + mi * 16 + g) * XLD + ks * 8 + t4;
                a[mi][0] = __float_as_uint(ap[0]);
                a[mi][2] = __float_as_uint(ap[4]);
                a[mi][1] = __float_as_uint(ap[8 * XLD]);
                a[mi][3] = __float_as_uint(ap[8 * XLD + 4]);
            }
            #pragma unroll
            for (int ni = 0; ni < 8; ni++) {
                const float* bp = Wt + (ks * 8 + t4) * WLD + warp_n * 64 + ni * 8 + g;
                unsigned bb[2] = { __float_as_uint(bp[0]), __float_as_uint(bp[4 * WLD]) };
                mma_tf32(c[0][ni], a[0], bb);
                mma_tf32(c[1][ni], a[1], bb);
            }
        }
        __syncthreads();
    }

    // epilogue: store tf32-rounded bits (identical numerics to converting at
    // the consuming mma). Out[(bb*H + h), s, d].
    const int bbatch = m0 / S;
    const int s0     = m0 % S;
    float* Ob = Out + ((size_t)(bbatch * H + h) * S + s0) * DH;
    #pragma unroll
    for (int mi = 0; mi < 2; mi++) {
        const int r0 = warp_m * 32 + mi * 16 + g;
        #pragma unroll
        for (int ni = 0; ni < 8; ni++) {
            const int col = warp_n * 64 + ni * 8 + 2 * t4;
            float2 v0, v1;
            v0.x = __uint_as_float(f2tf(c[mi][ni][0]));
            v0.y = __uint_as_float(f2tf(c[mi][ni][1]));
            v1.x = __uint_as_float(f2tf(c[mi][ni][2]));
            v1.y = __uint_as_float(f2tf(c[mi][ni][3]));
            *reinterpret_cast<float2*>(Ob + (size_t)r0 * DH + col)       = v0;
            *reinterpret_cast<float2*>(Ob + (size_t)(r0 + 8) * DH + col) = v1;
        }
    }
}

// ---------------------------------------------------------------------------
// Kernel 2: causal flash attention on tensor cores (mma.m16n8k8 tf32)
//   Q/K/V arrive pre-rounded to tf32 -> fragment loads are raw bit loads.
//   CTA = 64 q-rows of one (b,h). 8 warps = 4(m) x 2(n).
// ---------------------------------------------------------------------------
#define KLD 132
#define VLD 136
#define SLD 68
#define ATTN_SMEM_FLOATS (64*KLD + 2*64*KLD + 2*64*VLD + 64*SLD + 64 + 64 + 128 + 128)
#define ATTN_SMEM_BYTES  (ATTN_SMEM_FLOATS * 4)   // 189,952 B

__global__ __launch_bounds__(256, 1) void attn_kernel(float* __restrict__ out)
{
    extern __shared__ float sm[];
    float* Qs   = sm;                       // 64*132 (tf32 bits)
    float* Ks   = Qs + 64*KLD;              // 2 x 64*132 (tf32 bits)
    float* Vs   = Ks + 2*64*KLD;            // 2 x 64*136 (tf32 bits)
    float* Ss   = Vs + 2*64*VLD;            // 64*68 (tf32 bits of P)
    float* m_s  = Ss + 64*SLD;
    float* l_s  = m_s + 64;
    float* wmax = l_s + 64;
    float* wsum = wmax + 128;
    unsigned* Su = reinterpret_cast<unsigned*>(Ss);

    const int qb = blockIdx.x;
    const int bh = blockIdx.y;
    const int b  = bh >> 4;
    const int h  = bh & 15;
    const int q0 = qb * 64;
    const int tid  = threadIdx.x;
    const int lane = tid & 31;
    const int wid  = tid >> 5;
    const int warp_m = wid >> 1;
    const int warp_n = wid & 1;
    const int g  = lane >> 2;
    const int t4 = lane & 3;
    const int m0 = warp_m * 16;
    const int rlo = m0 + g;
    const int rhi = m0 + g + 8;

    if (tid < 64) { m_s[tid] = -3.0e38f; l_s[tid] = 0.0f; }

    {
        const float* Qg = g_Q + ((size_t)bh * S + q0) * DH;
        const float* Kg = g_K + ((size_t)bh * S) * DH;
        const float* Vg = g_V + ((size_t)bh * S) * DH;
        const int row = tid >> 2, c0 = tid & 3;
        #pragma unroll
        for (int i = 0; i < 8; i++) {
            const int col = (c0 + 4 * i) * 4;
            cp16(Qs + row * KLD + col, Qg + row * DH + col);
            cp16(Ks + row * KLD + col, Kg + row * DH + col);
            cp16(Vs + row * VLD + col, Vg + row * DH + col);
        }
        cp_commit();
    }

    float oacc[8][4];
    #pragma unroll
    for (int i = 0; i < 8; i++)
        #pragma unroll
        for (int j = 0; j < 4; j++) oacc[i][j] = 0.0f;

    const float scale = 0.08838834764831845f;  // 1/sqrt(128)

    for (int kb = 0; kb <= qb; kb++) {
        __syncthreads();
        if (kb < qb) {
            const int st = (kb + 1) & 1;
            const float* Kg = g_K + ((size_t)bh * S + (size_t)(kb + 1) * 64) * DH;
            const float* Vg = g_V + ((size_t)bh * S + (size_t)(kb + 1) * 64) * DH;
            float* Kd = Ks + st * (64 * KLD);
            float* Vd = Vs + st * (64 * VLD);
            const int row = tid >> 2, c0 = tid & 3;
            #pragma unroll
            for (int i = 0; i < 8; i++) {
                const int col = (c0 + 4 * i) * 4;
                cp16(Kd + row * KLD + col, Kg + row * DH + col);
                cp16(Vd + row * VLD + col, Vg + row * DH + col);
            }
            cp_commit();
            cp_wait1();
        } else {
            cp_wait0();
        }
        __syncthreads();

        const float* Kb_ = Ks + (kb & 1) * (64 * KLD);
        const float* Vb_ = Vs + (kb & 1) * (64 * VLD);

        // ---- scores: C = Q . K^T (raw tf32 bit loads, no cvt) ----
        float c[4][4];
        #pragma unroll
        for (int nf = 0; nf < 4; nf++)
            #pragma unroll
            for (int e = 0; e < 4; e++) c[nf][e] = 0.0f;

        #pragma unroll
        for (int ks = 0; ks < 16; ks++) {
            const float* qp = Qs + rlo * KLD + ks * 8 + t4;
            unsigned a[4];
            a[0] = __float_as_uint(qp[0]);
            a[2] = __float_as_uint(qp[4]);
            a[1] = __float_as_uint(qp[8 * KLD]);
            a[3] = __float_as_uint(qp[8 * KLD + 4]);
            #pragma unroll
            for (int nf = 0; nf < 4; nf++) {
                const float* kp = Kb_ + (warp_n * 32 + nf * 8 + g) * KLD + ks * 8 + t4;
                unsigned bb[2] = { __float_as_uint(kp[0]), __float_as_uint(kp[4]) };
                mma_tf32(c[nf], a, bb);
            }
        }

        float mx0 = -3.0e38f, mx1 = -3.0e38f;
        #pragma unroll
        for (int nf = 0; nf < 4; nf++) {
            const int col = warp_n * 32 + nf * 8 + 2 * t4;
            #pragma unroll
            for (int e = 0; e < 4; e++) c[nf][e] *= scale;
            if (kb == qb) {
                if (col     > rlo) c[nf][0] = -3.0e38f;
                if (col + 1 > rlo) c[nf][1] = -3.0e38f;
                if (col     > rhi) c[nf][2] = -3.0e38f;
                if (col + 1 > rhi) c[nf][3] = -3.0e38f;
            }
            mx0 = fmaxf(mx0, fmaxf(c[nf][0], c[nf][1]));
            mx1 = fmaxf(mx1, fmaxf(c[nf][2], c[nf][3]));
        }
        mx0 = fmaxf(mx0, __shfl_xor_sync(0xffffffffu, mx0, 1));
        mx0 = fmaxf(mx0, __shfl_xor_sync(0xffffffffu, mx0, 2));
        mx1 = fmaxf(mx1, __shfl_xor_sync(0xffffffffu, mx1, 1));
        mx1 = fmaxf(mx1, __shfl_xor_sync(0xffffffffu, mx1, 2));
        if (t4 == 0) {
            wmax[warp_n * 64 + rlo] = mx0;
            wmax[warp_n * 64 + rhi] = mx1;
        }
        __syncthreads();

        const float mo0 = m_s[rlo], mo1 = m_s[rhi];
        const float mn0 = fmaxf(mo0, fmaxf(wmax[rlo], wmax[64 + rlo]));
        const float mn1 = fmaxf(mo1, fmaxf(wmax[rhi], wmax[64 + rhi]));
        const float cr0 = __expf(mo0 - mn0);
        const float cr1 = __expf(mo1 - mn1);
        float sum0 = 0.0f, sum1 = 0.0f;
        #pragma unroll
        for (int nf = 0; nf < 4; nf++) {
            const int col = warp_n * 32 + nf * 8 + 2 * t4;
            const float p0 = __expf(c[nf][0] - mn0);
            const float p1 = __expf(c[nf][1] - mn0);
            const float p2 = __expf(c[nf][2] - mn1);
            const float p3 = __expf(c[nf][3] - mn1);
            sum0 += p0 + p1;
            sum1 += p2 + p3;
            uint2 lo = make_uint2(f2tf(p0), f2tf(p1));
            uint2 hi = make_uint2(f2tf(p2), f2tf(p3));
            *reinterpret_cast<uint2*>(Su + rlo * SLD + col) = lo;
            *reinterpret_cast<uint2*>(Su + rhi * SLD + col) = hi;
        }
        sum0 += __shfl_xor_sync(0xffffffffu, sum0, 1);
        sum0 += __shfl_xor_sync(0xffffffffu, sum0, 2);
        sum1 += __shfl_xor_sync(0xffffffffu, sum1, 1);
        sum1 += __shfl_xor_sync(0xffffffffu, sum1, 2);
        if (t4 == 0) {
            wsum[warp_n * 64 + rlo] = sum0;
            wsum[warp_n * 64 + rhi] = sum1;
        }
        #pragma unroll
        for (int nf = 0; nf < 8; nf++) {
            oacc[nf][0] *= cr0; oacc[nf][1] *= cr0;
            oacc[nf][2] *= cr1; oacc[nf][3] *= cr1;
        }
        __syncthreads();

        // ---- PV: O += P . V (V already tf32 bits) ----
        #pragma unroll
        for (int ks = 0; ks < 8; ks++) {
            const unsigned* sp = Su + rlo * SLD + ks * 8 + t4;
            unsigned a[4];
            a[0] = sp[0];
            a[2] = sp[4];
            a[1] = sp[8 * SLD];
            a[3] = sp[8 * SLD + 4];
            const float* vp0 = Vb_ + (ks * 8 + t4) * VLD + warp_n * 64 + g;
            const float* vp1 = vp0 + 4 * VLD;
            #pragma unroll
            for (int nf = 0; nf < 8; nf++) {
                unsigned bb[2] = { __float_as_uint(vp0[nf * 8]), __float_as_uint(vp1[nf * 8]) };
                mma_tf32(oacc[nf], a, bb);
            }
        }

        if (warp_n == 0 && t4 == 0) {
            m_s[rlo] = mn0;
            l_s[rlo] = l_s[rlo] * cr0 + wsum[rlo] + wsum[64 + rlo];
            m_s[rhi] = mn1;
            l_s[rhi] = l_s[rhi] * cr1 + wsum[rhi] + wsum[64 + rhi];
        }
    }

    __syncthreads();
    const float li0 = 1.0f / l_s[rlo];
    const float li1 = 1.0f / l_s[rhi];
    float* og0 = out + ((size_t)(b * S + q0 + rlo)) * (H * DH) + h * DH + warp_n * 64;
    float* og1 = out + ((size_t)(b * S + q0 + rhi)) * (H * DH) + h * DH + warp_n * 64;
    #pragma unroll
    for (int nf = 0; nf < 8; nf++) {
        const int col = nf * 8 + 2 * t4;
        float2 v0, v1;
        v0.x = rintf(oacc[nf][0] * li0 * 1.0e4f) * 1.0e-4f;
        v0.y = rintf(oacc[nf][1] * li0 * 1.0e4f) * 1.0e-4f;
        v1.x = rintf(oacc[nf][2] * li1 * 1.0e4f) * 1.0e-4f;
        v1.y = rintf(oacc[nf][3] * li1 * 1.0e4f) * 1.0e-4f;
        *reinterpret_cast<float2*>(og0 + col) = v0;
        *reinterpret_cast<float2*>(og1 + col) = v1;
    }
}

// ---------------------------------------------------------------------------
extern "C" void kernel_launch(void* const* d_in, const int* in_sizes, int n_in,
                              void* d_out, int out_size)
{
    const float* X  = (const float*)d_in[0];
    const float* Wq = (const float*)d_in[1];
    const float* Wk = (const float*)d_in[2];
    const float* Wv = (const float*)d_in[3];
    float* out = (float*)d_out;

    cudaFuncSetAttribute(qkv_kernel,  cudaFuncAttributeMaxDynamicSharedMemorySize, QKV_SMEM_BYTES);
    cudaFuncSetAttribute(attn_kernel, cudaFuncAttributeMaxDynamicSharedMemorySize, ATTN_SMEM_BYTES);

    // device-global destinations (resolve via symbol address on host is not
    // allowed in capture; use a tiny launch trick: kernels reference globals
    // directly, conversion kernels get raw pointers via cudaGetSymbolAddress)
    static float *pXc = nullptr, *pWq = nullptr, *pWk = nullptr, *pWv = nullptr;
    if (!pXc) {
        cudaGetSymbolAddress((void**)&pXc, g_Xc);
        cudaGetSymbolAddress((void**)&pWq, g_Wcq);
        cudaGetSymbolAddress((void**)&pWk, g_Wck);
        cudaGetSymbolAddress((void**)&pWv, g_Wcv);
    }

    tf32_conv<<<2048, 256>>>(X,  pXc, (int)((size_t)BS * E / 4));
    tf32_conv<<<1024, 256>>>(Wq, pWq, (int)((size_t)H * E * DH / 4));
    tf32_conv<<<1024, 256>>>(Wk, pWk, (int)((size_t)H * E * DH / 4));
    tf32_conv<<<1024, 256>>>(Wv, pWv, (int)((size_t)H * E * DH / 4));

    dim3 g1(H, BS / QM, 3);
    qkv_kernel<<<g1, 256, QKV_SMEM_BYTES>>>();

    dim3 g2(S / 64, B * H);
    attn_kernel<<<g2, 256, ATTN_SMEM_BYTES>>>(out);
}

// round 6
// speedup vs baseline: 16.1953x; 1.8339x over previous
#include <cuda_runtime.h>
#include <cuda_fp16.h>
#include <cstdint>
#include <cstddef>

// Problem constants
#define B   4
#define S   2048
#define E   2048
#define H   16
#define DH  128
#define BS  (B*S)   // 8192

// fp16 scratch
__device__ __half g_Q [(size_t)B*H*S*DH];          // [bh][S][DH]
__device__ __half g_K [(size_t)B*H*S*DH];          // [bh][S][DH]
__device__ __half g_Vt[(size_t)B*H*S*DH];          // [bh][DH][S]  (transposed)
__device__ __half g_Xh[(size_t)BS*E];              // [BS][E]
__device__ __half g_Wtq[(size_t)H*DH*E];           // [H][DH][E]   (transposed)
__device__ __half g_Wtk[(size_t)H*DH*E];
__device__ __half g_Wtv[(size_t)H*DH*E];

// ---------------------------------------------------------------------------
// helpers
// ---------------------------------------------------------------------------
__device__ __forceinline__ void cp16(void* smem_dst, const void* gmem_src) {
    unsigned int d = (unsigned int)__cvta_generic_to_shared(smem_dst);
    asm volatile("cp.async.cg.shared.global [%0], [%1], 16;\n" :: "r"(d), "l"(gmem_src));
}
__device__ __forceinline__ void cp_commit() { asm volatile("cp.async.commit_group;\n"); }
__device__ __forceinline__ void cp_wait1()  { asm volatile("cp.async.wait_group 1;\n"); }
__device__ __forceinline__ void cp_wait0()  { asm volatile("cp.async.wait_group 0;\n"); }

__device__ __forceinline__ void mma_f16(float c[4], const unsigned a[4], const unsigned b[2]) {
    asm volatile("mma.sync.aligned.m16n8k16.row.col.f32.f16.f16.f32 "
        "{%0,%1,%2,%3}, {%4,%5,%6,%7}, {%8,%9}, {%0,%1,%2,%3};"
        : "+f"(c[0]), "+f"(c[1]), "+f"(c[2]), "+f"(c[3])
        : "r"(a[0]), "r"(a[1]), "r"(a[2]), "r"(a[3]), "r"(b[0]), "r"(b[1]));
}
__device__ __forceinline__ unsigned ldb32(const __half* p) {
    return *reinterpret_cast<const unsigned*>(p);
}
__device__ __forceinline__ unsigned pack2(float lo, float hi) {
    __half2 h = __floats2half2_rn(lo, hi);
    return *reinterpret_cast<unsigned*>(&h);
}

// ---------------------------------------------------------------------------
// Kernel 0a: X f32 -> f16 elementwise
// ---------------------------------------------------------------------------
__global__ void convX(const float* __restrict__ src, __half* __restrict__ dst, int n4)
{
    const float4* s = (const float4*)src;
    uint2*        d = (uint2*)dst;
    for (int i = blockIdx.x * blockDim.x + threadIdx.x; i < n4; i += gridDim.x * blockDim.x) {
        float4 v = s[i];
        uint2 o;
        o.x = pack2(v.x, v.y);
        o.y = pack2(v.z, v.w);
        d[i] = o;
    }
}

// ---------------------------------------------------------------------------
// Kernel 0b: W [H][E][DH] f32 -> Wt [H][DH][E] f16 (tiled transpose)
//   grid (DH/32, E/32, 3*H), block (32, 8)
// ---------------------------------------------------------------------------
__global__ void convWT(const float* __restrict__ Wq, const float* __restrict__ Wk,
                       const float* __restrict__ Wv,
                       __half* __restrict__ Tq, __half* __restrict__ Tk,
                       __half* __restrict__ Tv)
{
    __shared__ float tile[32][33];
    const int zz = blockIdx.z;
    const int z  = zz >> 4;           // 0..2
    const int h  = zz & 15;
    const float* Wsrc = (z == 0 ? Wq : (z == 1 ? Wk : Wv)) + (size_t)h * E * DH;
    __half*      Tdst = (z == 0 ? Tq : (z == 1 ? Tk : Tv)) + (size_t)h * DH * E;

    const int d0 = blockIdx.x * 32;
    const int e0 = blockIdx.y * 32;
    const int tx = threadIdx.x, ty = threadIdx.y;

    #pragma unroll
    for (int j = 0; j < 4; j++) {
        int e = e0 + ty + j * 8;
        tile[ty + j * 8][tx] = Wsrc[(size_t)e * DH + d0 + tx];
    }
    __syncthreads();
    #pragma unroll
    for (int j = 0; j < 4; j++) {
        int d = d0 + ty + j * 8;
        Tdst[(size_t)d * E + e0 + tx] = __float2half(tile[tx][ty + j * 8]);
    }
}

// ---------------------------------------------------------------------------
// Kernel 1: QKV GEMM on mma.m16n8k16 f16/f32.
//   Block tile 128(M) x 128(N = one head) x 64(K halves), 256 threads,
//   8 warps = 4(m) x 2(n), warp tile 32x64. Double-buffered cp.async,
//   2 CTAs/SM. Smem strides 72 halves (144 B == 16 mod 128 -> conflict-free).
//   Q/K stored natural fp16; V stored transposed [bh][DH][S] fp16.
// ---------------------------------------------------------------------------
#define QKC 64
#define XLD2 72
#define WLD2 72
#define XST2 (128*XLD2)    // 9216 halves
#define WST2 (128*WLD2)    // 9216 halves
#define QKV_SMEM_BYTES ((2*(XST2+WST2))*2)   // 73,728 B

__global__ __launch_bounds__(256, 2) void qkv_kernel()
{
    extern __shared__ __half smh[];
    __half* Xs[2] = { smh,            smh + XST2 };
    __half* Ws[2] = { smh + 2*XST2,   smh + 2*XST2 + WST2 };

    const int h    = blockIdx.x;
    const int mblk = blockIdx.y;
    const int z    = blockIdx.z;

    const __half* Wb = (z == 0 ? g_Wtq : (z == 1 ? g_Wtk : g_Wtv)) + (size_t)h * DH * E;

    const int tx   = threadIdx.x;
    const int lane = tx & 31;
    const int wid  = tx >> 5;
    const int warp_m = wid >> 1;   // 0..3 : 32 rows
    const int warp_n = wid & 1;    // 0..1 : 64 cols
    const int g  = lane >> 2;
    const int t4 = lane & 3;
    const int m0 = mblk * 128;

    float c[2][8][4];
    #pragma unroll
    for (int mi = 0; mi < 2; mi++)
        #pragma unroll
        for (int ni = 0; ni < 8; ni++)
            #pragma unroll
            for (int e = 0; e < 4; e++) c[mi][ni][e] = 0.0f;

    const __half* Xg = g_Xh + (size_t)m0 * E;

    auto issue = [&](int kt, int st) {
        #pragma unroll
        for (int i = 0; i < 4; i++) {
            int idx  = tx + 256 * i;          // 0..1023
            int row  = idx >> 3;              // 0..127
            int col8 = (idx & 7) * 8;         // halves
            cp16(Xs[st] + row * XLD2 + col8, Xg + (size_t)row * E + kt * QKC + col8);
            cp16(Ws[st] + row * WLD2 + col8, Wb + (size_t)row * E + kt * QKC + col8);
        }
        cp_commit();
    };

    const int NK = E / QKC;   // 32
    issue(0, 0);

    for (int kt = 0; kt < NK; kt++) {
        const int st = kt & 1;
        if (kt + 1 < NK) { issue(kt + 1, st ^ 1); cp_wait1(); }
        else             { cp_wait0(); }
        __syncthreads();

        const __half* Xt = Xs[st];
        const __half* Wt = Ws[st];
        #pragma unroll
        for (int ks = 0; ks < 4; ks++) {
            unsigned a[2][4];
            #pragma unroll
            for (int mi = 0; mi < 2; mi++) {
                const __half* ap = Xt + (warp_m * 32 + mi * 16 + g) * XLD2 + ks * 16 + 2 * t4;
                a[mi][0] = ldb32(ap);
                a[mi][1] = ldb32(ap + 8 * XLD2);
                a[mi][2] = ldb32(ap + 8);
                a[mi][3] = ldb32(ap + 8 * XLD2 + 8);
            }
            #pragma unroll
            for (int ni = 0; ni < 8; ni++) {
                const __half* bp = Wt + (warp_n * 64 + ni * 8 + g) * WLD2 + ks * 16 + 2 * t4;
                unsigned bb[2] = { ldb32(bp), ldb32(bp + 8) };
                mma_f16(c[0][ni], a[0], bb);
                mma_f16(c[1][ni], a[1], bb);
            }
        }
        __syncthreads();
    }

    // epilogue
    const int bbatch = m0 / S;
    const int s0     = m0 % S;
    const int bh     = bbatch * H + h;
    if (z < 2) {
        __half* Ob = (z == 0 ? g_Q : g_K) + ((size_t)bh * S + s0) * DH;
        #pragma unroll
        for (int mi = 0; mi < 2; mi++) {
            const int r0 = warp_m * 32 + mi * 16 + g;
            #pragma unroll
            for (int ni = 0; ni < 8; ni++) {
                const int col = warp_n * 64 + ni * 8 + 2 * t4;
                *reinterpret_cast<unsigned*>(Ob + (size_t)r0 * DH + col)
                    = pack2(c[mi][ni][0], c[mi][ni][1]);
                *reinterpret_cast<unsigned*>(Ob + (size_t)(r0 + 8) * DH + col)
                    = pack2(c[mi][ni][2], c[mi][ni][3]);
            }
        }
    } else {
        // V transposed: g_Vt[bh][d][s]
        __half* Ob = g_Vt + (size_t)bh * DH * S + s0;
        #pragma unroll
        for (int mi = 0; mi < 2; mi++) {
            const int r0 = warp_m * 32 + mi * 16 + g;
            #pragma unroll
            for (int ni = 0; ni < 8; ni++) {
                const int col = warp_n * 64 + ni * 8 + 2 * t4;
                Ob[(size_t)col * S + r0]           = __float2half(c[mi][ni][0]);
                Ob[(size_t)(col + 1) * S + r0]     = __float2half(c[mi][ni][1]);
                Ob[(size_t)col * S + r0 + 8]       = __float2half(c[mi][ni][2]);
                Ob[(size_t)(col + 1) * S + r0 + 8] = __float2half(c[mi][ni][3]);
            }
        }
    }
}

// ---------------------------------------------------------------------------
// Kernel 2: causal flash attention on mma.m16n8k16 f16/f32.
//   CTA = 64 q-rows of one (b,h). 8 warps = 4(m) x 2(n). 2 CTAs/SM.
//   Q/K natural fp16, V transposed fp16 -> all fragment loads are b32.
// ---------------------------------------------------------------------------
#define QLD 136    // halves; 272 B == 16 mod 128
#define VLD 72     // halves; 144 B == 16 mod 128
#define PLD 72
#define ATTN_H (64*QLD + 2*64*QLD + 2*128*VLD + 64*PLD)   // halves: 49152
#define ATTN_SMEM_BYTES (ATTN_H*2 + (64+64+128+128)*4)    // 99,840 B

__global__ __launch_bounds__(256, 2) void attn_kernel(float* __restrict__ out)
{
    extern __shared__ __half smh[];
    __half* Qs  = smh;                    // 64 x QLD
    __half* Ks  = Qs + 64*QLD;            // 2 x 64 x QLD
    __half* VTs = Ks + 2*64*QLD;          // 2 x 128 x VLD
    __half* Ps  = VTs + 2*128*VLD;        // 64 x PLD
    float* m_s  = reinterpret_cast<float*>(smh + ATTN_H);
    float* l_s  = m_s + 64;
    float* wmax = l_s + 64;
    float* wsum = wmax + 128;

    const int qb = blockIdx.x;
    const int bh = blockIdx.y;
    const int b  = bh >> 4;
    const int h  = bh & 15;
    const int q0 = qb * 64;
    const int tid  = threadIdx.x;
    const int lane = tid & 31;
    const int wid  = tid >> 5;
    const int warp_m = wid >> 1;
    const int warp_n = wid & 1;
    const int g  = lane >> 2;
    const int t4 = lane & 3;
    const int rlo = warp_m * 16 + g;
    const int rhi = rlo + 8;

    if (tid < 64) { m_s[tid] = -3.0e38f; l_s[tid] = 0.0f; }

    // initial loads: Q + K0 + VT0
    {
        const __half* Qg = g_Q  + ((size_t)bh * S + q0) * DH;
        const __half* Kg = g_K  + ((size_t)bh * S) * DH;
        const __half* Vg = g_Vt + (size_t)bh * DH * S;   // [d][s]
        const int row = tid >> 2, c0 = tid & 3;          // Q/K: 64 rows
        const int vrow = tid >> 1, v0 = tid & 1;         // VT: 128 rows
        #pragma unroll
        for (int i = 0; i < 4; i++) {
            const int col = (c0 + 4 * i) * 8;
            cp16(Qs + row * QLD + col, Qg + row * DH + col);
            cp16(Ks + row * QLD + col, Kg + row * DH + col);
            const int vc = (v0 + 2 * i) * 8;
            cp16(VTs + vrow * VLD + vc, Vg + (size_t)vrow * S + vc);
        }
        cp_commit();
    }

    float oacc[8][4];
    #pragma unroll
    for (int i = 0; i < 8; i++)
        #pragma unroll
        for (int j = 0; j < 4; j++) oacc[i][j] = 0.0f;

    const float scale = 0.08838834764831845f;  // 1/sqrt(128)

    for (int kb = 0; kb <= qb; kb++) {
        __syncthreads();
        if (kb < qb) {
            const int st = (kb + 1) & 1;
            const __half* Kg = g_K  + ((size_t)bh * S + (size_t)(kb + 1) * 64) * DH;
            const __half* Vg = g_Vt + (size_t)bh * DH * S + (size_t)(kb + 1) * 64;
            __half* Kd = Ks  + st * (64 * QLD);
            __half* Vd = VTs + st * (128 * VLD);
            const int row = tid >> 2, c0 = tid & 3;
            const int vrow = tid >> 1, v0 = tid & 1;
            #pragma unroll
            for (int i = 0; i < 4; i++) {
                const int col = (c0 + 4 * i) * 8;
                cp16(Kd + row * QLD + col, Kg + row * DH + col);
                const int vc = (v0 + 2 * i) * 8;
                cp16(Vd + vrow * VLD + vc, Vg + (size_t)vrow * S + vc);
            }
            cp_commit();
            cp_wait1();
        } else {
            cp_wait0();
        }
        __syncthreads();

        const __half* Kb_ = Ks  + (kb & 1) * (64 * QLD);
        const __half* Vb_ = VTs + (kb & 1) * (128 * VLD);

        // ---- scores: C = Q . K^T ----
        float c[4][4];
        #pragma unroll
        for (int nf = 0; nf < 4; nf++)
            #pragma unroll
            for (int e = 0; e < 4; e++) c[nf][e] = 0.0f;

        #pragma unroll
        for (int ks = 0; ks < 8; ks++) {
            const __half* qp = Qs + rlo * QLD + ks * 16 + 2 * t4;
            unsigned a[4];
            a[0] = ldb32(qp);
            a[1] = ldb32(qp + 8 * QLD);
            a[2] = ldb32(qp + 8);
            a[3] = ldb32(qp + 8 * QLD + 8);
            #pragma unroll
            for (int nf = 0; nf < 4; nf++) {
                const __half* kp = Kb_ + (warp_n * 32 + nf * 8 + g) * QLD + ks * 16 + 2 * t4;
                unsigned bb[2] = { ldb32(kp), ldb32(kp + 8) };
                mma_f16(c[nf], a, bb);
            }
        }

        float mx0 = -3.0e38f, mx1 = -3.0e38f;
        #pragma unroll
        for (int nf = 0; nf < 4; nf++) {
            const int col = warp_n * 32 + nf * 8 + 2 * t4;
            #pragma unroll
            for (int e = 0; e < 4; e++) c[nf][e] *= scale;
            if (kb == qb) {
                if (col     > rlo) c[nf][0] = -3.0e38f;
                if (col + 1 > rlo) c[nf][1] = -3.0e38f;
                if (col     > rhi) c[nf][2] = -3.0e38f;
                if (col + 1 > rhi) c[nf][3] = -3.0e38f;
            }
            mx0 = fmaxf(mx0, fmaxf(c[nf][0], c[nf][1]));
            mx1 = fmaxf(mx1, fmaxf(c[nf][2], c[nf][3]));
        }
        mx0 = fmaxf(mx0, __shfl_xor_sync(0xffffffffu, mx0, 1));
        mx0 = fmaxf(mx0, __shfl_xor_sync(0xffffffffu, mx0, 2));
        mx1 = fmaxf(mx1, __shfl_xor_sync(0xffffffffu, mx1, 1));
        mx1 = fmaxf(mx1, __shfl_xor_sync(0xffffffffu, mx1, 2));
        if (t4 == 0) {
            wmax[warp_n * 64 + rlo] = mx0;
            wmax[warp_n * 64 + rhi] = mx1;
        }
        __syncthreads();

        const float mo0 = m_s[rlo], mo1 = m_s[rhi];
        const float mn0 = fmaxf(mo0, fmaxf(wmax[rlo], wmax[64 + rlo]));
        const float mn1 = fmaxf(mo1, fmaxf(wmax[rhi], wmax[64 + rhi]));
        const float cr0 = __expf(mo0 - mn0);
        const float cr1 = __expf(mo1 - mn1);
        float sum0 = 0.0f, sum1 = 0.0f;
        #pragma unroll
        for (int nf = 0; nf < 4; nf++) {
            const int col = warp_n * 32 + nf * 8 + 2 * t4;
            const float p0 = __expf(c[nf][0] - mn0);
            const float p1 = __expf(c[nf][1] - mn0);
            const float p2 = __expf(c[nf][2] - mn1);
            const float p3 = __expf(c[nf][3] - mn1);
            sum0 += p0 + p1;
            sum1 += p2 + p3;
            *reinterpret_cast<unsigned*>(Ps + rlo * PLD + col) = pack2(p0, p1);
            *reinterpret_cast<unsigned*>(Ps + rhi * PLD + col) = pack2(p2, p3);
        }
        sum0 += __shfl_xor_sync(0xffffffffu, sum0, 1);
        sum0 += __shfl_xor_sync(0xffffffffu, sum0, 2);
        sum1 += __shfl_xor_sync(0xffffffffu, sum1, 1);
        sum1 += __shfl_xor_sync(0xffffffffu, sum1, 2);
        if (t4 == 0) {
            wsum[warp_n * 64 + rlo] = sum0;
            wsum[warp_n * 64 + rhi] = sum1;
        }
        #pragma unroll
        for (int nf = 0; nf < 8; nf++) {
            oacc[nf][0] *= cr0; oacc[nf][1] *= cr0;
            oacc[nf][2] *= cr1; oacc[nf][3] *= cr1;
        }
        __syncthreads();

        // ---- PV: O += P . V  (A = P row-major, B = V^T) ----
        #pragma unroll
        for (int ks = 0; ks < 4; ks++) {
            const __half* sp = Ps + rlo * PLD + ks * 16 + 2 * t4;
            unsigned a[4];
            a[0] = ldb32(sp);
            a[1] = ldb32(sp + 8 * PLD);
            a[2] = ldb32(sp + 8);
            a[3] = ldb32(sp + 8 * PLD + 8);
            #pragma unroll
            for (int nf = 0; nf < 8; nf++) {
                const __half* vp = Vb_ + (warp_n * 64 + nf * 8 + g) * VLD + ks * 16 + 2 * t4;
                unsigned bb[2] = { ldb32(vp), ldb32(vp + 8) };
                mma_f16(oacc[nf], a, bb);
            }
        }

        if (warp_n == 0 && t4 == 0) {
            m_s[rlo] = mn0;
            l_s[rlo] = l_s[rlo] * cr0 + wsum[rlo] + wsum[64 + rlo];
            m_s[rhi] = mn1;
            l_s[rhi] = l_s[rhi] * cr1 + wsum[rhi] + wsum[64 + rhi];
        }
    }

    __syncthreads();
    const float li0 = 1.0f / l_s[rlo];
    const float li1 = 1.0f / l_s[rhi];
    float* og0 = out + ((size_t)(b * S + q0 + rlo)) * (H * DH) + h * DH + warp_n * 64;
    float* og1 = out + ((size_t)(b * S + q0 + rhi)) * (H * DH) + h * DH + warp_n * 64;
    #pragma unroll
    for (int nf = 0; nf < 8; nf++) {
        const int col = nf * 8 + 2 * t4;
        float2 v0, v1;
        v0.x = rintf(oacc[nf][0] * li0 * 1.0e4f) * 1.0e-4f;
        v0.y = rintf(oacc[nf][1] * li0 * 1.0e4f) * 1.0e-4f;
        v1.x = rintf(oacc[nf][2] * li1 * 1.0e4f) * 1.0e-4f;
        v1.y = rintf(oacc[nf][3] * li1 * 1.0e4f) * 1.0e-4f;
        *reinterpret_cast<float2*>(og0 + col) = v0;
        *reinterpret_cast<float2*>(og1 + col) = v1;
    }
}

// ---------------------------------------------------------------------------
extern "C" void kernel_launch(void* const* d_in, const int* in_sizes, int n_in,
                              void* d_out, int out_size)
{
    const float* X  = (const float*)d_in[0];
    const float* Wq = (const float*)d_in[1];
    const float* Wk = (const float*)d_in[2];
    const float* Wv = (const float*)d_in[3];
    float* out = (float*)d_out;

    cudaFuncSetAttribute(qkv_kernel,  cudaFuncAttributeMaxDynamicSharedMemorySize, QKV_SMEM_BYTES);
    cudaFuncSetAttribute(attn_kernel, cudaFuncAttributeMaxDynamicSharedMemorySize, ATTN_SMEM_BYTES);

    static __half *pXh = nullptr, *pWq = nullptr, *pWk = nullptr, *pWv = nullptr;
    if (!pXh) {
        cudaGetSymbolAddress((void**)&pXh, g_Xh);
        cudaGetSymbolAddress((void**)&pWq, g_Wtq);
        cudaGetSymbolAddress((void**)&pWk, g_Wtk);
        cudaGetSymbolAddress((void**)&pWv, g_Wtv);
    }

    convX<<<2048, 256>>>(X, pXh, (int)((size_t)BS * E / 4));
    dim3 gt(DH / 32, E / 32, 3 * H);
    convWT<<<gt, dim3(32, 8)>>>(Wq, Wk, Wv, pWq, pWk, pWv);

    dim3 g1(H, BS / 128, 3);
    qkv_kernel<<<g1, 256, QKV_SMEM_BYTES>>>();

    dim3 g2(S / 64, B * H);
    attn_kernel<<<g2, 256, ATTN_SMEM_BYTES>>>(out);
}

// round 7
// speedup vs baseline: 19.9143x; 1.2296x over previous
#include <cuda_runtime.h>
#include <cuda_fp16.h>
#include <cstdint>
#include <cstddef>

// Problem constants
#define B   4
#define S   2048
#define E   2048
#define H   16
#define DH  128
#define BS  (B*S)   // 8192

// fp16 scratch
__device__ __half g_Q [(size_t)B*H*S*DH];          // [bh][S][DH]
__device__ __half g_K [(size_t)B*H*S*DH];          // [bh][S][DH]
__device__ __half g_Vt[(size_t)B*H*S*DH];          // [bh][DH][S]  (transposed)
__device__ __half g_Xh[(size_t)BS*E];              // [BS][E]
__device__ __half g_Wtq[(size_t)H*DH*E];           // [H][DH][E]   (transposed)
__device__ __half g_Wtk[(size_t)H*DH*E];
__device__ __half g_Wtv[(size_t)H*DH*E];

// ---------------------------------------------------------------------------
// helpers
// ---------------------------------------------------------------------------
__device__ __forceinline__ void cp16(void* smem_dst, const void* gmem_src) {
    unsigned int d = (unsigned int)__cvta_generic_to_shared(smem_dst);
    asm volatile("cp.async.cg.shared.global [%0], [%1], 16;\n" :: "r"(d), "l"(gmem_src));
}
__device__ __forceinline__ void cp_commit() { asm volatile("cp.async.commit_group;\n"); }
__device__ __forceinline__ void cp_wait1()  { asm volatile("cp.async.wait_group 1;\n"); }
__device__ __forceinline__ void cp_wait0()  { asm volatile("cp.async.wait_group 0;\n"); }

__device__ __forceinline__ unsigned smaddr(const void* p) {
    return (unsigned)__cvta_generic_to_shared(p);
}
__device__ __forceinline__ void ldsm4(unsigned& r0, unsigned& r1, unsigned& r2, unsigned& r3,
                                      unsigned addr) {
    asm volatile("ldmatrix.sync.aligned.m8n8.x4.shared.b16 {%0,%1,%2,%3}, [%4];"
        : "=r"(r0), "=r"(r1), "=r"(r2), "=r"(r3) : "r"(addr));
}
__device__ __forceinline__ void mma_f16(float c[4], const unsigned a[4], const unsigned b[2]) {
    asm volatile("mma.sync.aligned.m16n8k16.row.col.f32.f16.f16.f32 "
        "{%0,%1,%2,%3}, {%4,%5,%6,%7}, {%8,%9}, {%0,%1,%2,%3};"
        : "+f"(c[0]), "+f"(c[1]), "+f"(c[2]), "+f"(c[3])
        : "r"(a[0]), "r"(a[1]), "r"(a[2]), "r"(a[3]), "r"(b[0]), "r"(b[1]));
}
__device__ __forceinline__ unsigned pack2(float lo, float hi) {
    __half2 h = __floats2half2_rn(lo, hi);
    return *reinterpret_cast<unsigned*>(&h);
}

// ---------------------------------------------------------------------------
// Kernel 0a: X f32 -> f16 elementwise
// ---------------------------------------------------------------------------
__global__ void convX(const float* __restrict__ src, __half* __restrict__ dst, int n4)
{
    const float4* s = (const float4*)src;
    uint2*        d = (uint2*)dst;
    for (int i = blockIdx.x * blockDim.x + threadIdx.x; i < n4; i += gridDim.x * blockDim.x) {
        float4 v = s[i];
        uint2 o;
        o.x = pack2(v.x, v.y);
        o.y = pack2(v.z, v.w);
        d[i] = o;
    }
}

// ---------------------------------------------------------------------------
// Kernel 0b: W [H][E][DH] f32 -> Wt [H][DH][E] f16 (tiled transpose)
// ---------------------------------------------------------------------------
__global__ void convWT(const float* __restrict__ Wq, const float* __restrict__ Wk,
                       const float* __restrict__ Wv,
                       __half* __restrict__ Tq, __half* __restrict__ Tk,
                       __half* __restrict__ Tv)
{
    __shared__ float tile[32][33];
    const int zz = blockIdx.z;
    const int z  = zz >> 4;
    const int h  = zz & 15;
    const float* Wsrc = (z == 0 ? Wq : (z == 1 ? Wk : Wv)) + (size_t)h * E * DH;
    __half*      Tdst = (z == 0 ? Tq : (z == 1 ? Tk : Tv)) + (size_t)h * DH * E;

    const int d0 = blockIdx.x * 32;
    const int e0 = blockIdx.y * 32;
    const int tx = threadIdx.x, ty = threadIdx.y;

    #pragma unroll
    for (int j = 0; j < 4; j++) {
        int e = e0 + ty + j * 8;
        tile[ty + j * 8][tx] = Wsrc[(size_t)e * DH + d0 + tx];
    }
    __syncthreads();
    #pragma unroll
    for (int j = 0; j < 4; j++) {
        int d = d0 + ty + j * 8;
        Tdst[(size_t)d * E + e0 + tx] = __float2half(tile[tx][ty + j * 8]);
    }
}

// ---------------------------------------------------------------------------
// Kernel 1: QKV GEMM, mma.m16n8k16 f16/f32 + ldmatrix fragment loads.
//   Block 128(M) x 128(N) x 64(K halves), 8 warps = 4(m) x 2(n).
// ---------------------------------------------------------------------------
#define QKC 64
#define XLD2 72
#define WLD2 72
#define XST2 (128*XLD2)
#define WST2 (128*WLD2)
#define QKV_SMEM_BYTES ((2*(XST2+WST2))*2)   // 73,728 B

__global__ __launch_bounds__(256, 2) void qkv_kernel()
{
    extern __shared__ __half smh[];
    __half* Xs[2] = { smh,            smh + XST2 };
    __half* Ws[2] = { smh + 2*XST2,   smh + 2*XST2 + WST2 };

    const int h    = blockIdx.x;
    const int mblk = blockIdx.y;
    const int z    = blockIdx.z;

    const __half* Wb = (z == 0 ? g_Wtq : (z == 1 ? g_Wtk : g_Wtv)) + (size_t)h * DH * E;

    const int tx   = threadIdx.x;
    const int lane = tx & 31;
    const int wid  = tx >> 5;
    const int warp_m = wid >> 1;
    const int warp_n = wid & 1;
    const int g  = lane >> 2;
    const int t4 = lane & 3;
    const int m0 = mblk * 128;

    // ldmatrix lane address decomposition (loop-invariant)
    const int a_row  = (lane & 7) + ((lane >> 3) & 1) * 8;
    const int a_col  = (lane >> 4) * 8;
    const int b_row  = (lane & 7) + (lane >> 4) * 8;
    const int b_col  = ((lane >> 3) & 1) * 8;

    float c[2][8][4];
    #pragma unroll
    for (int mi = 0; mi < 2; mi++)
        #pragma unroll
        for (int ni = 0; ni < 8; ni++)
            #pragma unroll
            for (int e = 0; e < 4; e++) c[mi][ni][e] = 0.0f;

    const __half* Xg = g_Xh + (size_t)m0 * E;

    auto issue = [&](int kt, int st) {
        #pragma unroll
        for (int i = 0; i < 4; i++) {
            int idx  = tx + 256 * i;
            int row  = idx >> 3;
            int col8 = (idx & 7) * 8;
            cp16(Xs[st] + row * XLD2 + col8, Xg + (size_t)row * E + kt * QKC + col8);
            cp16(Ws[st] + row * WLD2 + col8, Wb + (size_t)row * E + kt * QKC + col8);
        }
        cp_commit();
    };

    const int NK = E / QKC;   // 32
    issue(0, 0);

    for (int kt = 0; kt < NK; kt++) {
        const int st = kt & 1;
        if (kt + 1 < NK) { issue(kt + 1, st ^ 1); cp_wait1(); }
        else             { cp_wait0(); }
        __syncthreads();

        const __half* Xt = Xs[st];
        const __half* Wt = Ws[st];
        #pragma unroll
        for (int ks = 0; ks < 4; ks++) {
            unsigned a[2][4];
            #pragma unroll
            for (int mi = 0; mi < 2; mi++)
                ldsm4(a[mi][0], a[mi][1], a[mi][2], a[mi][3],
                      smaddr(Xt + (warp_m * 32 + mi * 16 + a_row) * XLD2 + ks * 16 + a_col));
            #pragma unroll
            for (int pr = 0; pr < 4; pr++) {
                unsigned b4[4];
                ldsm4(b4[0], b4[1], b4[2], b4[3],
                      smaddr(Wt + (warp_n * 64 + pr * 16 + b_row) * WLD2 + ks * 16 + b_col));
                unsigned b01[2] = { b4[0], b4[1] };
                unsigned b23[2] = { b4[2], b4[3] };
                mma_f16(c[0][2 * pr],     a[0], b01);
                mma_f16(c[0][2 * pr + 1], a[0], b23);
                mma_f16(c[1][2 * pr],     a[1], b01);
                mma_f16(c[1][2 * pr + 1], a[1], b23);
            }
        }
        __syncthreads();
    }

    // epilogue
    const int bbatch = m0 / S;
    const int s0     = m0 % S;
    const int bh     = bbatch * H + h;
    if (z < 2) {
        __half* Ob = (z == 0 ? g_Q : g_K) + ((size_t)bh * S + s0) * DH;
        #pragma unroll
        for (int mi = 0; mi < 2; mi++) {
            const int r0 = warp_m * 32 + mi * 16 + g;
            #pragma unroll
            for (int ni = 0; ni < 8; ni++) {
                const int col = warp_n * 64 + ni * 8 + 2 * t4;
                *reinterpret_cast<unsigned*>(Ob + (size_t)r0 * DH + col)
                    = pack2(c[mi][ni][0], c[mi][ni][1]);
                *reinterpret_cast<unsigned*>(Ob + (size_t)(r0 + 8) * DH + col)
                    = pack2(c[mi][ni][2], c[mi][ni][3]);
            }
        }
    } else {
        __half* Ob = g_Vt + (size_t)bh * DH * S + s0;
        #pragma unroll
        for (int mi = 0; mi < 2; mi++) {
            const int r0 = warp_m * 32 + mi * 16 + g;
            #pragma unroll
            for (int ni = 0; ni < 8; ni++) {
                const int col = warp_n * 64 + ni * 8 + 2 * t4;
                Ob[(size_t)col * S + r0]           = __float2half(c[mi][ni][0]);
                Ob[(size_t)(col + 1) * S + r0]     = __float2half(c[mi][ni][1]);
                Ob[(size_t)col * S + r0 + 8]       = __float2half(c[mi][ni][2]);
                Ob[(size_t)(col + 1) * S + r0 + 8] = __float2half(c[mi][ni][3]);
            }
        }
    }
}

// ---------------------------------------------------------------------------
// Kernel 2: causal flash attention, FA2-style warp layout.
//   CTA = 128 q-rows of one (b,h); 8 warps, each owns 16 FULL rows.
//   Softmax warp-private (m,l in registers); P stays in registers (QK
//   accumulator layout == PV A-fragment layout). K/V double-buffered,
//   ldmatrix for all smem fragment loads. 2 syncthreads per KV tile.
// ---------------------------------------------------------------------------
#define QLD 136    // halves; 272 B == 16 mod 128
#define VLD 72     // halves; 144 B == 16 mod 128
#define ATTN_SMEM_BYTES ((128*QLD + 2*64*QLD + 2*128*VLD) * 2)   // 106,496 B

__global__ __launch_bounds__(256, 1) void attn_kernel(float* __restrict__ out)
{
    extern __shared__ __half smh[];
    __half* Qs  = smh;                    // 128 x QLD
    __half* Ks  = Qs + 128*QLD;           // 2 x 64 x QLD
    __half* VTs = Ks + 2*64*QLD;          // 2 x 128 x VLD

    const int qb = blockIdx.x;
    const int bh = blockIdx.y;
    const int b  = bh >> 4;
    const int h  = bh & 15;
    const int q0 = qb * 128;
    const int tid  = threadIdx.x;
    const int lane = tid & 31;
    const int wid  = tid >> 5;
    const int g  = lane >> 2;
    const int t4 = lane & 3;
    const int rlo = wid * 16 + g;
    const int rhi = rlo + 8;

    const int a_row = wid * 16 + (lane & 7) + ((lane >> 3) & 1) * 8;
    const int a_col = (lane >> 4) * 8;
    const int b_row = (lane & 7) + (lane >> 4) * 8;
    const int b_col = ((lane >> 3) & 1) * 8;

    // initial loads: Q (128 rows) + K0 (64 rows) + VT0 (128 rows x 64 cols)
    {
        const __half* Qg = g_Q  + ((size_t)bh * S + q0) * DH;
        const __half* Kg = g_K  + ((size_t)bh * S) * DH;
        const __half* Vg = g_Vt + (size_t)bh * DH * S;
        const int qrow = tid >> 1, q1 = tid & 1;
        #pragma unroll
        for (int i = 0; i < 4; i++) {
            const int col = (q1 + 2 * i) * 8;
            cp16(Qs + qrow * QLD + col,      Qg + (size_t)qrow * DH + col);
            cp16(Qs + qrow * QLD + col + 64, Qg + (size_t)qrow * DH + col + 64);
        }
        const int krow = tid >> 2, k1 = tid & 3;
        #pragma unroll
        for (int i = 0; i < 2; i++) {
            const int col = (k1 + 4 * i) * 16;
            cp16(Ks + krow * QLD + col,     Kg + (size_t)krow * DH + col);
            cp16(Ks + krow * QLD + col + 8, Kg + (size_t)krow * DH + col + 8);
        }
        const int vrow = tid >> 1, v1 = tid & 1;
        #pragma unroll
        for (int i = 0; i < 4; i++) {
            const int vc = (v1 + 2 * i) * 8;
            cp16(VTs + vrow * VLD + vc, Vg + (size_t)vrow * S + vc);
        }
        cp_commit();
    }

    float oacc[16][4];
    #pragma unroll
    for (int i = 0; i < 16; i++)
        #pragma unroll
        for (int j = 0; j < 4; j++) oacc[i][j] = 0.0f;

    float m0r = -3.0e38f, m1r = -3.0e38f, l0r = 0.0f, l1r = 0.0f;
    const float scale = 0.08838834764831845f;  // 1/sqrt(128)

    const int NT = 2 * qb + 2;
    for (int kb = 0; kb < NT; kb++) {
        __syncthreads();
        if (kb + 1 < NT) {
            const int st = (kb + 1) & 1;
            const __half* Kg = g_K  + ((size_t)bh * S + (size_t)(kb + 1) * 64) * DH;
            const __half* Vg = g_Vt + (size_t)bh * DH * S + (size_t)(kb + 1) * 64;
            __half* Kd = Ks  + st * (64 * QLD);
            __half* Vd = VTs + st * (128 * VLD);
            const int krow = tid >> 2, k1 = tid & 3;
            #pragma unroll
            for (int i = 0; i < 2; i++) {
                const int col = (k1 + 4 * i) * 16;
                cp16(Kd + krow * QLD + col,     Kg + (size_t)krow * DH + col);
                cp16(Kd + krow * QLD + col + 8, Kg + (size_t)krow * DH + col + 8);
            }
            const int vrow = tid >> 1, v1 = tid & 1;
            #pragma unroll
            for (int i = 0; i < 4; i++) {
                const int vc = (v1 + 2 * i) * 8;
                cp16(Vd + vrow * VLD + vc, Vg + (size_t)vrow * S + vc);
            }
            cp_commit();
            cp_wait1();
        } else {
            cp_wait0();
        }
        __syncthreads();

        const __half* Kb_ = Ks  + (kb & 1) * (64 * QLD);
        const __half* Vb_ = VTs + (kb & 1) * (128 * VLD);
        const int k0 = kb * 64;

        // ---- scores: C[16 rows x 64 keys] = Q . K^T ----
        float c[8][4];
        #pragma unroll
        for (int nf = 0; nf < 8; nf++)
            #pragma unroll
            for (int e = 0; e < 4; e++) c[nf][e] = 0.0f;

        #pragma unroll
        for (int ks = 0; ks < 8; ks++) {
            unsigned a[4];
            ldsm4(a[0], a[1], a[2], a[3],
                  smaddr(Qs + a_row * QLD + ks * 16 + a_col));
            #pragma unroll
            for (int pr = 0; pr < 4; pr++) {
                unsigned b4[4];
                ldsm4(b4[0], b4[1], b4[2], b4[3],
                      smaddr(Kb_ + (pr * 16 + b_row) * QLD + ks * 16 + b_col));
                unsigned b01[2] = { b4[0], b4[1] };
                unsigned b23[2] = { b4[2], b4[3] };
                mma_f16(c[2 * pr],     a, b01);
                mma_f16(c[2 * pr + 1], a, b23);
            }
        }

        // scale + causal mask
        #pragma unroll
        for (int nf = 0; nf < 8; nf++)
            #pragma unroll
            for (int e = 0; e < 4; e++) c[nf][e] *= scale;
        if (kb >= 2 * qb) {
            #pragma unroll
            for (int nf = 0; nf < 8; nf++) {
                const int key = k0 + nf * 8 + 2 * t4;
                if (key     > q0 + rlo) c[nf][0] = -1.0e30f;
                if (key + 1 > q0 + rlo) c[nf][1] = -1.0e30f;
                if (key     > q0 + rhi) c[nf][2] = -1.0e30f;
                if (key + 1 > q0 + rhi) c[nf][3] = -1.0e30f;
            }
        }

        // ---- warp-private online softmax ----
        float mx0 = -3.0e38f, mx1 = -3.0e38f;
        #pragma unroll
        for (int nf = 0; nf < 8; nf++) {
            mx0 = fmaxf(mx0, fmaxf(c[nf][0], c[nf][1]));
            mx1 = fmaxf(mx1, fmaxf(c[nf][2], c[nf][3]));
        }
        mx0 = fmaxf(mx0, __shfl_xor_sync(0xffffffffu, mx0, 1));
        mx0 = fmaxf(mx0, __shfl_xor_sync(0xffffffffu, mx0, 2));
        mx1 = fmaxf(mx1, __shfl_xor_sync(0xffffffffu, mx1, 1));
        mx1 = fmaxf(mx1, __shfl_xor_sync(0xffffffffu, mx1, 2));
        const float mn0 = fmaxf(m0r, mx0);
        const float mn1 = fmaxf(m1r, mx1);
        const float cr0 = __expf(m0r - mn0);
        const float cr1 = __expf(m1r - mn1);

        float sum0 = 0.0f, sum1 = 0.0f;
        #pragma unroll
        for (int nf = 0; nf < 8; nf++) {
            c[nf][0] = __expf(c[nf][0] - mn0);
            c[nf][1] = __expf(c[nf][1] - mn0);
            c[nf][2] = __expf(c[nf][2] - mn1);
            c[nf][3] = __expf(c[nf][3] - mn1);
            sum0 += c[nf][0] + c[nf][1];
            sum1 += c[nf][2] + c[nf][3];
        }
        sum0 += __shfl_xor_sync(0xffffffffu, sum0, 1);
        sum0 += __shfl_xor_sync(0xffffffffu, sum0, 2);
        sum1 += __shfl_xor_sync(0xffffffffu, sum1, 1);
        sum1 += __shfl_xor_sync(0xffffffffu, sum1, 2);
        l0r = l0r * cr0 + sum0;
        l1r = l1r * cr1 + sum1;
        m0r = mn0;
        m1r = mn1;

        // P -> fp16 a-fragments, directly in registers
        unsigned pa[4][4];
        #pragma unroll
        for (int ks = 0; ks < 4; ks++) {
            pa[ks][0] = pack2(c[2 * ks][0],     c[2 * ks][1]);
            pa[ks][1] = pack2(c[2 * ks][2],     c[2 * ks][3]);
            pa[ks][2] = pack2(c[2 * ks + 1][0], c[2 * ks + 1][1]);
            pa[ks][3] = pack2(c[2 * ks + 1][2], c[2 * ks + 1][3]);
        }

        // rescale O accumulators
        #pragma unroll
        for (int nf = 0; nf < 16; nf++) {
            oacc[nf][0] *= cr0; oacc[nf][1] *= cr0;
            oacc[nf][2] *= cr1; oacc[nf][3] *= cr1;
        }

        // ---- PV: O += P . V  (B from transposed V) ----
        #pragma unroll
        for (int ks = 0; ks < 4; ks++) {
            #pragma unroll
            for (int pr = 0; pr < 8; pr++) {
                unsigned b4[4];
                ldsm4(b4[0], b4[1], b4[2], b4[3],
                      smaddr(Vb_ + (pr * 16 + b_row) * VLD + ks * 16 + b_col));
                unsigned b01[2] = { b4[0], b4[1] };
                unsigned b23[2] = { b4[2], b4[3] };
                mma_f16(oacc[2 * pr],     pa[ks], b01);
                mma_f16(oacc[2 * pr + 1], pa[ks], b23);
            }
        }
    }

    // epilogue: normalize, round(x,4), write [B,S,H*DH]
    const float li0 = 1.0f / l0r;
    const float li1 = 1.0f / l1r;
    float* og0 = out + ((size_t)(b * S + q0 + rlo)) * (H * DH) + h * DH;
    float* og1 = out + ((size_t)(b * S + q0 + rhi)) * (H * DH) + h * DH;
    #pragma unroll
    for (int nf = 0; nf < 16; nf++) {
        const int col = nf * 8 + 2 * t4;
        float2 v0, v1;
        v0.x = rintf(oacc[nf][0] * li0 * 1.0e4f) * 1.0e-4f;
        v0.y = rintf(oacc[nf][1] * li0 * 1.0e4f) * 1.0e-4f;
        v1.x = rintf(oacc[nf][2] * li1 * 1.0e4f) * 1.0e-4f;
        v1.y = rintf(oacc[nf][3] * li1 * 1.0e4f) * 1.0e-4f;
        *reinterpret_cast<float2*>(og0 + col) = v0;
        *reinterpret_cast<float2*>(og1 + col) = v1;
    }
}

// ---------------------------------------------------------------------------
extern "C" void kernel_launch(void* const* d_in, const int* in_sizes, int n_in,
                              void* d_out, int out_size)
{
    const float* X  = (const float*)d_in[0];
    const float* Wq = (const float*)d_in[1];
    const float* Wk = (const float*)d_in[2];
    const float* Wv = (const float*)d_in[3];
    float* out = (float*)d_out;

    cudaFuncSetAttribute(qkv_kernel,  cudaFuncAttributeMaxDynamicSharedMemorySize, QKV_SMEM_BYTES);
    cudaFuncSetAttribute(attn_kernel, cudaFuncAttributeMaxDynamicSharedMemorySize, ATTN_SMEM_BYTES);

    static __half *pXh = nullptr, *pWq = nullptr, *pWk = nullptr, *pWv = nullptr;
    if (!pXh) {
        cudaGetSymbolAddress((void**)&pXh, g_Xh);
        cudaGetSymbolAddress((void**)&pWq, g_Wtq);
        cudaGetSymbolAddress((void**)&pWk, g_Wtk);
        cudaGetSymbolAddress((void**)&pWv, g_Wtv);
    }

    convX<<<2048, 256>>>(X, pXh, (int)((size_t)BS * E / 4));
    dim3 gt(DH / 32, E / 32, 3 * H);
    convWT<<<gt, dim3(32, 8)>>>(Wq, Wk, Wv, pWq, pWk, pWv);

    dim3 g1(H, BS / 128, 3);
    qkv_kernel<<<g1, 256, QKV_SMEM_BYTES>>>();

    dim3 g2(S / 128, B * H);
    attn_kernel<<<g2, 256, ATTN_SMEM_BYTES>>>(out);
}

// round 9
// speedup vs baseline: 20.3869x; 1.0237x over previous
#include <cuda_runtime.h>
#include <cuda_fp16.h>
#include <cstdint>
#include <cstddef>

// Problem constants
#define B   4
#define S   2048
#define E   2048
#define H   16
#define DH  128
#define BS  (B*S)   // 8192

// fp16 scratch
__device__ __half g_Q [(size_t)B*H*S*DH];          // [bh][S][DH]
__device__ __half g_K [(size_t)B*H*S*DH];          // [bh][S][DH]
__device__ __half g_Vt[(size_t)B*H*S*DH];          // [bh][DH][S]  (transposed)
__device__ __half g_Xh[(size_t)BS*E];              // [BS][E]
__device__ __half g_Wtq[(size_t)H*DH*E];           // [H][DH][E]   (transposed)
__device__ __half g_Wtk[(size_t)H*DH*E];
__device__ __half g_Wtv[(size_t)H*DH*E];

// ---------------------------------------------------------------------------
// helpers
// ---------------------------------------------------------------------------
__device__ __forceinline__ unsigned smaddr(const void* p) {
    return (unsigned)__cvta_generic_to_shared(p);
}
__device__ __forceinline__ void cp16(void* smem_dst, const void* gmem_src) {
    unsigned d = smaddr(smem_dst);
    asm volatile("cp.async.cg.shared.global [%0], [%1], 16;\n" :: "r"(d), "l"(gmem_src));
}
__device__ __forceinline__ void cp_commit() { asm volatile("cp.async.commit_group;\n"); }
__device__ __forceinline__ void cp_wait1()  { asm volatile("cp.async.wait_group 1;\n"); }
__device__ __forceinline__ void cp_wait0()  { asm volatile("cp.async.wait_group 0;\n"); }

__device__ __forceinline__ void ldsm4(unsigned& r0, unsigned& r1, unsigned& r2, unsigned& r3,
                                      unsigned addr) {
    asm volatile("ldmatrix.sync.aligned.m8n8.x4.shared.b16 {%0,%1,%2,%3}, [%4];"
        : "=r"(r0), "=r"(r1), "=r"(r2), "=r"(r3) : "r"(addr));
}
__device__ __forceinline__ void mma_f16(float c[4], const unsigned a[4], const unsigned b[2]) {
    asm volatile("mma.sync.aligned.m16n8k16.row.col.f32.f16.f16.f32 "
        "{%0,%1,%2,%3}, {%4,%5,%6,%7}, {%8,%9}, {%0,%1,%2,%3};"
        : "+f"(c[0]), "+f"(c[1]), "+f"(c[2]), "+f"(c[3])
        : "r"(a[0]), "r"(a[1]), "r"(a[2]), "r"(a[3]), "r"(b[0]), "r"(b[1]));
}
__device__ __forceinline__ unsigned pack2(float lo, float hi) {
    __half2 h = __floats2half2_rn(lo, hi);
    return *reinterpret_cast<unsigned*>(&h);
}
// 2^lo, 2^hi as packed fp16 (lo in low half)
__device__ __forceinline__ unsigned exp2h2(float lo, float hi) {
    unsigned r;
    asm("{\n\t.reg .b32 t;\n\t"
        "cvt.rn.f16x2.f32 t, %2, %1;\n\t"    // first src -> high half
        "ex2.approx.f16x2 %0, t;\n\t}"
        : "=r"(r) : "f"(lo), "f"(hi));
    return r;
}

// ---------------------------------------------------------------------------
// Kernel 0a: X f32 -> f16 elementwise
// ---------------------------------------------------------------------------
__global__ void convX(const float* __restrict__ src, __half* __restrict__ dst, int n4)
{
    const float4* s = (const float4*)src;
    uint2*        d = (uint2*)dst;
    for (int i = blockIdx.x * blockDim.x + threadIdx.x; i < n4; i += gridDim.x * blockDim.x) {
        float4 v = s[i];
        uint2 o;
        o.x = pack2(v.x, v.y);
        o.y = pack2(v.z, v.w);
        d[i] = o;
    }
}

// ---------------------------------------------------------------------------
// Kernel 0b: W [H][E][DH] f32 -> Wt [H][DH][E] f16 (tiled transpose)
// ---------------------------------------------------------------------------
__global__ void convWT(const float* __restrict__ Wq, const float* __restrict__ Wk,
                       const float* __restrict__ Wv,
                       __half* __restrict__ Tq, __half* __restrict__ Tk,
                       __half* __restrict__ Tv)
{
    __shared__ float tile[32][33];
    const int zz = blockIdx.z;
    const int z  = zz >> 4;
    const int h  = zz & 15;
    const float* Wsrc = (z == 0 ? Wq : (z == 1 ? Wk : Wv)) + (size_t)h * E * DH;
    __half*      Tdst = (z == 0 ? Tq : (z == 1 ? Tk : Tv)) + (size_t)h * DH * E;

    const int d0 = blockIdx.x * 32;
    const int e0 = blockIdx.y * 32;
    const int tx = threadIdx.x, ty = threadIdx.y;

    #pragma unroll
    for (int j = 0; j < 4; j++) {
        int e = e0 + ty + j * 8;
        tile[ty + j * 8][tx] = Wsrc[(size_t)e * DH + d0 + tx];
    }
    __syncthreads();
    #pragma unroll
    for (int j = 0; j < 4; j++) {
        int d = d0 + ty + j * 8;
        Tdst[(size_t)d * E + e0 + tx] = __float2half(tile[tx][ty + j * 8]);
    }
}

// ---------------------------------------------------------------------------
// Kernel 1: QKV GEMM, mma.m16n8k16 f16/f32 + ldmatrix, 3-stage cp.async ring
//   (single __syncthreads per K chunk). Block 128(M) x 128(N) x 64(K halves),
//   8 warps = 4(m) x 2(n), 2 CTAs/SM.
// ---------------------------------------------------------------------------
#define QKC 64
#define XLD2 72
#define WLD2 72
#define XST2 (128*XLD2)
#define WST2 (128*WLD2)
#define QKV_SMEM_BYTES ((3*(XST2+WST2))*2)   // 110,592 B

__global__ __launch_bounds__(256, 2) void qkv_kernel()
{
    extern __shared__ __half smh[];
    __half* Xs[3] = { smh, smh + XST2, smh + 2*XST2 };
    __half* Ws[3] = { smh + 3*XST2, smh + 3*XST2 + WST2, smh + 3*XST2 + 2*WST2 };

    const int h    = blockIdx.x;
    const int mblk = blockIdx.y;
    const int z    = blockIdx.z;

    const __half* Wb = (z == 0 ? g_Wtq : (z == 1 ? g_Wtk : g_Wtv)) + (size_t)h * DH * E;

    const int tx   = threadIdx.x;
    const int lane = tx & 31;
    const int wid  = tx >> 5;
    const int warp_m = wid >> 1;
    const int warp_n = wid & 1;
    const int g  = lane >> 2;
    const int t4 = lane & 3;
    const int m0 = mblk * 128;

    const int a_row  = (lane & 7) + ((lane >> 3) & 1) * 8;
    const int a_col  = (lane >> 4) * 8;
    const int b_row  = (lane & 7) + (lane >> 4) * 8;
    const int b_col  = ((lane >> 3) & 1) * 8;

    float c[2][8][4];
    #pragma unroll
    for (int mi = 0; mi < 2; mi++)
        #pragma unroll
        for (int ni = 0; ni < 8; ni++)
            #pragma unroll
            for (int e = 0; e < 4; e++) c[mi][ni][e] = 0.0f;

    const __half* Xg = g_Xh + (size_t)m0 * E;

    auto issue = [&](int kt, int st) {
        #pragma unroll
        for (int i = 0; i < 4; i++) {
            int idx  = tx + 256 * i;
            int row  = idx >> 3;
            int col8 = (idx & 7) * 8;
            cp16(Xs[st] + row * XLD2 + col8, Xg + (size_t)row * E + kt * QKC + col8);
            cp16(Ws[st] + row * WLD2 + col8, Wb + (size_t)row * E + kt * QKC + col8);
        }
        cp_commit();
    };

    const int NK = E / QKC;   // 32
    issue(0, 0);
    issue(1, 1);

    for (int kt = 0; kt < NK; kt++) {
        if (kt + 1 < NK) cp_wait1(); else cp_wait0();
        __syncthreads();
        if (kt + 2 < NK) issue(kt + 2, (kt + 2) % 3);

        const __half* Xt = Xs[kt % 3];
        const __half* Wt = Ws[kt % 3];
        #pragma unroll
        for (int ks = 0; ks < 4; ks++) {
            unsigned a[2][4];
            #pragma unroll
            for (int mi = 0; mi < 2; mi++)
                ldsm4(a[mi][0], a[mi][1], a[mi][2], a[mi][3],
                      smaddr(Xt + (warp_m * 32 + mi * 16 + a_row) * XLD2 + ks * 16 + a_col));
            #pragma unroll
            for (int pr = 0; pr < 4; pr++) {
                unsigned b4[4];
                ldsm4(b4[0], b4[1], b4[2], b4[3],
                      smaddr(Wt + (warp_n * 64 + pr * 16 + b_row) * WLD2 + ks * 16 + b_col));
                unsigned b01[2] = { b4[0], b4[1] };
                unsigned b23[2] = { b4[2], b4[3] };
                mma_f16(c[0][2 * pr],     a[0], b01);
                mma_f16(c[0][2 * pr + 1], a[0], b23);
                mma_f16(c[1][2 * pr],     a[1], b01);
                mma_f16(c[1][2 * pr + 1], a[1], b23);
            }
        }
    }

    // epilogue
    const int bbatch = m0 / S;
    const int s0     = m0 % S;
    const int bh     = bbatch * H + h;
    if (z < 2) {
        __half* Ob = (z == 0 ? g_Q : g_K) + ((size_t)bh * S + s0) * DH;
        #pragma unroll
        for (int mi = 0; mi < 2; mi++) {
            const int r0 = warp_m * 32 + mi * 16 + g;
            #pragma unroll
            for (int ni = 0; ni < 8; ni++) {
                const int col = warp_n * 64 + ni * 8 + 2 * t4;
                *reinterpret_cast<unsigned*>(Ob + (size_t)r0 * DH + col)
                    = pack2(c[mi][ni][0], c[mi][ni][1]);
                *reinterpret_cast<unsigned*>(Ob + (size_t)(r0 + 8) * DH + col)
                    = pack2(c[mi][ni][2], c[mi][ni][3]);
            }
        }
    } else {
        __half* Ob = g_Vt + (size_t)bh * DH * S + s0;
        #pragma unroll
        for (int mi = 0; mi < 2; mi++) {
            const int r0 = warp_m * 32 + mi * 16 + g;
            #pragma unroll
            for (int ni = 0; ni < 8; ni++) {
                const int col = warp_n * 64 + ni * 8 + 2 * t4;
                Ob[(size_t)col * S + r0]           = __float2half(c[mi][ni][0]);
                Ob[(size_t)(col + 1) * S + r0]     = __float2half(c[mi][ni][1]);
                Ob[(size_t)col * S + r0 + 8]       = __float2half(c[mi][ni][2]);
                Ob[(size_t)(col + 1) * S + r0 + 8] = __float2half(c[mi][ni][3]);
            }
        }
    }
}

// ---------------------------------------------------------------------------
// Kernel 2: causal flash attention, FA2 warp layout.
//   CTA = 128 q-rows of one (b,h); 8 warps x 16 full rows. Q frags hoisted.
//   3-stage K/V ring, ONE __syncthreads per KV tile. Softmax via
//   ex2.approx.f16x2 (log2e folded into scale); row-sum l accumulated by an
//   extra ones-B mma (rescales with O, exact FlashAttention recurrence).
// ---------------------------------------------------------------------------
#define QLD 136    // halves; 272 B == 16 mod 128 -> conflict-free ldmatrix
#define VLD 72     // halves; 144 B == 16 mod 128
#define KSTG (64*QLD)
#define VSTG (128*VLD)
#define ATTN_SMEM_BYTES ((128*QLD + 3*KSTG + 3*VSTG) * 2)   // 142,336 B

#define SCALE_LOG2E 0.12751744654974748f   // log2(e)/sqrt(128)

__global__ __launch_bounds__(256, 1) void attn_kernel(float* __restrict__ out)
{
    extern __shared__ __half smh[];
    __half* Qs  = smh;                    // 128 x QLD
    __half* Ks  = Qs + 128*QLD;           // 3 x 64 x QLD
    __half* VTs = Ks + 3*KSTG;            // 3 x 128 x VLD  (V transposed [d][s])

    const int qb = blockIdx.x;
    const int bh = blockIdx.y;
    const int b  = bh >> 4;
    const int h  = bh & 15;
    const int q0 = qb * 128;
    const int tid  = threadIdx.x;
    const int lane = tid & 31;
    const int wid  = tid >> 5;
    const int g  = lane >> 2;
    const int t4 = lane & 3;
    const int rlo = wid * 16 + g;
    const int rhi = rlo + 8;

    const int a_row = wid * 16 + (lane & 7) + ((lane >> 3) & 1) * 8;
    const int a_col = (lane >> 4) * 8;
    const int b_row = (lane & 7) + (lane >> 4) * 8;
    const int b_col = ((lane >> 3) & 1) * 8;

    const __half* Kg0 = g_K  + (size_t)bh * S * DH;
    const __half* Vg0 = g_Vt + (size_t)bh * DH * S;

    auto issue_kv = [&](int kb, int st) {
        const __half* Kg = Kg0 + (size_t)kb * 64 * DH;
        const __half* Vg = Vg0 + (size_t)kb * 64;
        __half* Kd = Ks  + st * KSTG;
        __half* Vd = VTs + st * VSTG;
        const int krow = tid >> 2, k1 = tid & 3;
        #pragma unroll
        for (int i = 0; i < 2; i++) {
            const int col = (k1 + 4 * i) * 16;
            cp16(Kd + krow * QLD + col,     Kg + (size_t)krow * DH + col);
            cp16(Kd + krow * QLD + col + 8, Kg + (size_t)krow * DH + col + 8);
        }
        const int vrow = tid >> 1, v1 = tid & 1;
        #pragma unroll
        for (int i = 0; i < 4; i++) {
            const int vc = (v1 + 2 * i) * 8;
            cp16(Vd + vrow * VLD + vc, Vg + (size_t)vrow * S + vc);
        }
        cp_commit();
    };

    // group 0: Q + K0/V0 ; group 1: K1/V1
    {
        const __half* Qg = g_Q + ((size_t)bh * S + q0) * DH;
        const int qrow = tid >> 1, q1 = tid & 1;
        #pragma unroll
        for (int i = 0; i < 4; i++) {
            const int col = (q1 + 2 * i) * 8;
            cp16(Qs + qrow * QLD + col,      Qg + (size_t)qrow * DH + col);
            cp16(Qs + qrow * QLD + col + 64, Qg + (size_t)qrow * DH + col + 64);
        }
        issue_kv(0, 0);   // commits Q + KV0 together
    }
    issue_kv(1, 1);

    float oacc[16][4];
    #pragma unroll
    for (int i = 0; i < 16; i++)
        #pragma unroll
        for (int j = 0; j < 4; j++) oacc[i][j] = 0.0f;
    float lacc[4] = {0.f, 0.f, 0.f, 0.f};

    unsigned qa[8][4];
    float m0r = -3.0e38f, m1r = -3.0e38f;
    const unsigned ONES2 = 0x3C003C00u;   // half2(1,1)
    const unsigned onesb[2] = { ONES2, ONES2 };

    const int NT = 2 * qb + 2;
    for (int kb = 0; kb < NT; kb++) {
        if (kb + 1 < NT) cp_wait1(); else cp_wait0();
        __syncthreads();
        if (kb + 2 < NT) issue_kv(kb + 2, (kb + 2) % 3);

        if (kb == 0) {   // hoist Q fragments once
            #pragma unroll
            for (int ks = 0; ks < 8; ks++)
                ldsm4(qa[ks][0], qa[ks][1], qa[ks][2], qa[ks][3],
                      smaddr(Qs + a_row * QLD + ks * 16 + a_col));
        }

        const __half* Kb_ = Ks  + (kb % 3) * KSTG;
        const __half* Vb_ = VTs + (kb % 3) * VSTG;
        const int k0 = kb * 64;

        // ---- scores ----
        float c[8][4];
        #pragma unroll
        for (int nf = 0; nf < 8; nf++)
            #pragma unroll
            for (int e = 0; e < 4; e++) c[nf][e] = 0.0f;

        #pragma unroll
        for (int ks = 0; ks < 8; ks++) {
            #pragma unroll
            for (int pr = 0; pr < 4; pr++) {
                unsigned b4[4];
                ldsm4(b4[0], b4[1], b4[2], b4[3],
                      smaddr(Kb_ + (pr * 16 + b_row) * QLD + ks * 16 + b_col));
                unsigned b01[2] = { b4[0], b4[1] };
                unsigned b23[2] = { b4[2], b4[3] };
                mma_f16(c[2 * pr],     qa[ks], b01);
                mma_f16(c[2 * pr + 1], qa[ks], b23);
            }
        }

        // scale (log2 domain) + causal mask
        #pragma unroll
        for (int nf = 0; nf < 8; nf++)
            #pragma unroll
            for (int e = 0; e < 4; e++) c[nf][e] *= SCALE_LOG2E;
        if (kb >= 2 * qb) {
            #pragma unroll
            for (int nf = 0; nf < 8; nf++) {
                const int key = k0 + nf * 8 + 2 * t4;
                if (key     > q0 + rlo) c[nf][0] = -1.0e30f;
                if (key + 1 > q0 + rlo) c[nf][1] = -1.0e30f;
                if (key     > q0 + rhi) c[nf][2] = -1.0e30f;
                if (key + 1 > q0 + rhi) c[nf][3] = -1.0e30f;
            }
        }

        // ---- warp-private online softmax (base-2) ----
        float mx0 = -3.0e38f, mx1 = -3.0e38f;
        #pragma unroll
        for (int nf = 0; nf < 8; nf++) {
            mx0 = fmaxf(mx0, fmaxf(c[nf][0], c[nf][1]));
            mx1 = fmaxf(mx1, fmaxf(c[nf][2], c[nf][3]));
        }
        mx0 = fmaxf(mx0, __shfl_xor_sync(0xffffffffu, mx0, 1));
        mx0 = fmaxf(mx0, __shfl_xor_sync(0xffffffffu, mx0, 2));
        mx1 = fmaxf(mx1, __shfl_xor_sync(0xffffffffu, mx1, 1));
        mx1 = fmaxf(mx1, __shfl_xor_sync(0xffffffffu, mx1, 2));
        const float mn0 = fmaxf(m0r, mx0);
        const float mn1 = fmaxf(m1r, mx1);
        const float cr0 = exp2f(m0r - mn0);
        const float cr1 = exp2f(m1r - mn1);
        m0r = mn0;
        m1r = mn1;

        // probabilities straight to fp16 a-fragments (2^x, packed)
        unsigned pa[4][4];
        #pragma unroll
        for (int ks = 0; ks < 4; ks++) {
            pa[ks][0] = exp2h2(c[2 * ks][0] - mn0,     c[2 * ks][1] - mn0);
            pa[ks][1] = exp2h2(c[2 * ks][2] - mn1,     c[2 * ks][3] - mn1);
            pa[ks][2] = exp2h2(c[2 * ks + 1][0] - mn0, c[2 * ks + 1][1] - mn0);
            pa[ks][3] = exp2h2(c[2 * ks + 1][2] - mn1, c[2 * ks + 1][3] - mn1);
        }

        // rescale O and l accumulators
        #pragma unroll
        for (int nf = 0; nf < 16; nf++) {
            oacc[nf][0] *= cr0; oacc[nf][1] *= cr0;
            oacc[nf][2] *= cr1; oacc[nf][3] *= cr1;
        }
        lacc[0] *= cr0; lacc[1] *= cr0; lacc[2] *= cr1; lacc[3] *= cr1;

        // ---- PV + row-sum mma ----
        #pragma unroll
        for (int ks = 0; ks < 4; ks++) {
            #pragma unroll
            for (int pr = 0; pr < 8; pr++) {
                unsigned b4[4];
                ldsm4(b4[0], b4[1], b4[2], b4[3],
                      smaddr(Vb_ + (pr * 16 + b_row) * VLD + ks * 16 + b_col));
                unsigned b01[2] = { b4[0], b4[1] };
                unsigned b23[2] = { b4[2], b4[3] };
                mma_f16(oacc[2 * pr],     pa[ks], b01);
                mma_f16(oacc[2 * pr + 1], pa[ks], b23);
            }
            mma_f16(lacc, pa[ks], onesb);   // l += P . 1
        }
    }

    // epilogue: normalize, round(x,4), write [B,S,H*DH]
    const float li0 = 1.0f / lacc[0];
    const float li1 = 1.0f / lacc[2];
    float* og0 = out + ((size_t)(b * S + q0 + rlo)) * (H * DH) + h * DH;
    float* og1 = out + ((size_t)(b * S + q0 + rhi)) * (H * DH) + h * DH;
    #pragma unroll
    for (int nf = 0; nf < 16; nf++) {
        const int col = nf * 8 + 2 * t4;
        float2 v0, v1;
        v0.x = rintf(oacc[nf][0] * li0 * 1.0e4f) * 1.0e-4f;
        v0.y = rintf(oacc[nf][1] * li0 * 1.0e4f) * 1.0e-4f;
        v1.x = rintf(oacc[nf][2] * li1 * 1.0e4f) * 1.0e-4f;
        v1.y = rintf(oacc[nf][3] * li1 * 1.0e4f) * 1.0e-4f;
        *reinterpret_cast<float2*>(og0 + col) = v0;
        *reinterpret_cast<float2*>(og1 + col) = v1;
    }
}

// ---------------------------------------------------------------------------
extern "C" void kernel_launch(void* const* d_in, const int* in_sizes, int n_in,
                              void* d_out, int out_size)
{
    const float* X  = (const float*)d_in[0];
    const float* Wq = (const float*)d_in[1];
    const float* Wk = (const float*)d_in[2];
    const float* Wv = (const float*)d_in[3];
    float* out = (float*)d_out;

    cudaFuncSetAttribute(qkv_kernel,  cudaFuncAttributeMaxDynamicSharedMemorySize, QKV_SMEM_BYTES);
    cudaFuncSetAttribute(attn_kernel, cudaFuncAttributeMaxDynamicSharedMemorySize, ATTN_SMEM_BYTES);

    static __half *pXh = nullptr, *pWq = nullptr, *pWk = nullptr, *pWv = nullptr;
    if (!pXh) {
        cudaGetSymbolAddress((void**)&pXh, g_Xh);
        cudaGetSymbolAddress((void**)&pWq, g_Wtq);
        cudaGetSymbolAddress((void**)&pWk, g_Wtk);
        cudaGetSymbolAddress((void**)&pWv, g_Wtv);
    }

    convX<<<2048, 256>>>(X, pXh, (int)((size_t)BS * E / 4));
    dim3 gt(DH / 32, E / 32, 3 * H);
    convWT<<<gt, dim3(32, 8)>>>(Wq, Wk, Wv, pWq, pWk, pWv);

    dim3 g1(H, BS / 128, 3);
    qkv_kernel<<<g1, 256, QKV_SMEM_BYTES>>>();

    dim3 g2(S / 128, B * H);
    attn_kernel<<<g2, 256, ATTN_SMEM_BYTES>>>(out);
}